// round 15
// baseline (speedup 1.0000x reference)
#include <cuda_runtime.h>
#include <cuda_bf16.h>
#include <cstdint>

// ---------------- problem constants ----------------
#define NLAYERS 4
#define BB 8
#define MM 512
#define SS 1024
#define HH 768
#define KH 12
#define DD 64
#define FFD 3072
#define VV 32000
#define TT 1536   // S + M
#define KVS (2*HH)   // fused K|V column count

typedef __nv_bfloat16 bf16;

// ---------------- scratch (device globals; no runtime alloc) ----------------
__device__ float g_h  [BB*MM*HH];
__device__ float g_t2 [BB*MM*HH];

__device__ __align__(16) bf16 g_pposbf[(long)BB*MM*KH*SS];   // 100 MB
__device__ __align__(16) bf16 g_logbf [(long)BB*MM*VV];      // 262 MB bf16 logits

__device__ __align__(16) bf16 g_cachebf[(long)NLAYERS*BB*SS*HH]; // 48 MB bf16 cache
__device__ __align__(16) bf16 g_hbf   [BB*MM*HH];
__device__ __align__(16) bf16 g_qbf   [BB*MM*HH];
__device__ __align__(16) bf16 g_kvbf  [(long)BB*TT*KVS];
__device__ __align__(16) bf16 g_aobf  [BB*MM*HH];
__device__ __align__(16) bf16 g_ffbf  [BB*MM*FFD];
__device__ __align__(16) bf16 g_pet   [DD*SS];

// bf16 weights, NATURAL [K][N] layout (no transpose)
__device__ __align__(16) bf16 g_wq  [NLAYERS*HH*HH];
__device__ __align__(16) bf16 g_wkv [NLAYERS*HH*KVS];   // [K=768][N=1536] per layer
__device__ __align__(16) bf16 g_wo  [NLAYERS*HH*HH];
__device__ __align__(16) bf16 g_wf1 [NLAYERS*HH*FFD];
__device__ __align__(16) bf16 g_wf2 [NLAYERS*FFD*HH];
__device__ __align__(16) bf16 g_wout[(long)HH*VV];

// ---------------- small helpers ----------------
__device__ __forceinline__ uint32_t smem_u32(const void* p) {
    uint32_t a;
    asm("{ .reg .u64 t; cvta.to.shared.u64 t, %1; cvt.u32.u64 %0, t; }" : "=r"(a) : "l"(p));
    return a;
}
__device__ __forceinline__ void ldsm_x4(uint32_t& r0, uint32_t& r1, uint32_t& r2, uint32_t& r3,
                                        uint32_t addr) {
    asm volatile("ldmatrix.sync.aligned.m8n8.x4.shared.b16 {%0,%1,%2,%3}, [%4];"
                 : "=r"(r0), "=r"(r1), "=r"(r2), "=r"(r3) : "r"(addr));
}
__device__ __forceinline__ void ldsm_x4_t(uint32_t& r0, uint32_t& r1, uint32_t& r2, uint32_t& r3,
                                          uint32_t addr) {
    asm volatile("ldmatrix.sync.aligned.m8n8.x4.trans.shared.b16 {%0,%1,%2,%3}, [%4];"
                 : "=r"(r0), "=r"(r1), "=r"(r2), "=r"(r3) : "r"(addr));
}
__device__ __forceinline__ void mma16816(float* c, const uint32_t* a, uint32_t b0, uint32_t b1) {
    asm volatile("mma.sync.aligned.m16n8k16.row.col.f32.bf16.bf16.f32 "
                 "{%0,%1,%2,%3}, {%4,%5,%6,%7}, {%8,%9}, {%0,%1,%2,%3};"
                 : "+f"(c[0]), "+f"(c[1]), "+f"(c[2]), "+f"(c[3])
                 : "r"(a[0]), "r"(a[1]), "r"(a[2]), "r"(a[3]), "r"(b0), "r"(b1));
}
#define CP_ASYNC16(dst, src) \
    asm volatile("cp.async.cg.shared.global [%0], [%1], 16;" :: "r"(dst), "l"(src))
#define CP_COMMIT() asm volatile("cp.async.commit_group;" ::: "memory")
#define CP_WAIT(N)  asm volatile("cp.async.wait_group %0;" :: "n"(N) : "memory")

// ---------------- reduction helpers ----------------
__device__ __forceinline__ float blockReduceSum(float v, float* sh) {
    __syncthreads();
    int lane = threadIdx.x & 31, w = threadIdx.x >> 5;
    #pragma unroll
    for (int o = 16; o; o >>= 1) v += __shfl_xor_sync(0xffffffffu, v, o);
    if (lane == 0) sh[w] = v;
    __syncthreads();
    int nw = (blockDim.x + 31) >> 5;
    v = (threadIdx.x < nw) ? sh[threadIdx.x] : 0.f;
    if (w == 0) {
        #pragma unroll
        for (int o = 16; o; o >>= 1) v += __shfl_xor_sync(0xffffffffu, v, o);
        if (lane == 0) sh[0] = v;
    }
    __syncthreads();
    return sh[0];
}

// ---------------- fp32 -> bf16 streaming conversion (same layout) ----------------
__global__ __launch_bounds__(256)
void conv_bf16_kernel(const float* __restrict__ src, bf16* __restrict__ dst, long n4) {
    long i = (long)blockIdx.x * blockDim.x + threadIdx.x;
    if (i >= n4) return;
    float4 v = ((const float4*)src)[i];
    __nv_bfloat162 p0 = __floats2bfloat162_rn(v.x, v.y);
    __nv_bfloat162 p1 = __floats2bfloat162_rn(v.z, v.w);
    uint2 pk;
    pk.x = *(uint32_t*)&p0;
    pk.y = *(uint32_t*)&p1;
    ((uint2*)dst)[i] = pk;
}

// ---------------- Wk|Wv interleave -> fused [K=768][N=1536] per layer ----------------
__global__ __launch_bounds__(256)
void conv_kv_kernel(const float* __restrict__ Wk, const float* __restrict__ Wv,
                    bf16* __restrict__ dst) {
    // one float4 (4 n-values) per thread; total NL*HH*KVS/4
    long i = (long)blockIdx.x * blockDim.x + threadIdx.x;
    const long per_lk = KVS / 4;               // 384 float4 per (l,k) row
    const long total = (long)NLAYERS * HH * per_lk;
    if (i >= total) return;
    long lk = i / per_lk;
    int nc = (int)(i % per_lk);
    int n = nc * 4;
    const float* src = (n < HH) ? (Wk + lk * HH + n) : (Wv + lk * HH + (n - HH));
    float4 v = *(const float4*)src;
    __nv_bfloat162 p0 = __floats2bfloat162_rn(v.x, v.y);
    __nv_bfloat162 p1 = __floats2bfloat162_rn(v.z, v.w);
    uint2 pk;
    pk.x = *(uint32_t*)&p0;
    pk.y = *(uint32_t*)&p1;
    *(uint2*)(dst + lk * KVS + n) = pk;
}

// ---------------- embedding (fp32 + bf16) ----------------
__global__ void embed_kernel(const int* __restrict__ x, const float* __restrict__ emb,
                             float* __restrict__ h, bf16* __restrict__ hbf) {
    int row = blockIdx.x;
    int tok = x[row];
    const float* e = emb + (long)tok * HH;
    float* hp = h + (long)row * HH;
    bf16* hb = hbf + (long)row * HH;
    for (int i = threadIdx.x; i < HH; i += blockDim.x) {
        float v = e[i];
        hp[i] = v;
        hb[i] = __float2bfloat16_rn(v);
    }
}

// ================= GEMM: 128x128x64 tile, 4 warps (2m x 2n), warp tile 64x64 ======
// A: [M][K] row-major (K-major smem, 128B rows, XOR swizzle).
// B: [K][N] row-major (trans smem tile [64 k][128 n], 256B rows, perm swizzle,
//    fragments via ldmatrix.trans — same pattern as the FA kernel's P@V).
#define BKS 64
#define STG128 32768u
#define GEMM_DSMEM (3 * 32768)

__device__ __forceinline__ void cp_stage(
    const bf16* __restrict__ Ag, const bf16* __restrict__ Bg,
    int Kd, int N, int koff, uint32_t st, int tid)
{
    #pragma unroll
    for (int i = 0; i < 8; i++) {
        int id = tid + i * 128;
        int r = id >> 3, c = id & 7;
        uint32_t off = (uint32_t)(r * 128 + ((c ^ (r & 7)) << 4));
        CP_ASYNC16(st + off, Ag + (long)r * Kd + koff + c * 8);
    }
    uint32_t sb = st + 16384u;
    #pragma unroll
    for (int i = 0; i < 8; i++) {
        int id = tid + i * 128;
        int r = id >> 4, c = id & 15;
        uint32_t pc = (uint32_t)((c & 8) | ((c & 7) ^ (r & 7)));
        CP_ASYNC16(sb + (uint32_t)(r * 256) + (pc << 4),
                   Bg + (long)(koff + r) * N + c * 8);
    }
}

__device__ __forceinline__ void load_frags(
    uint32_t aB, uint32_t bB, int ks, int wm, int wn, int lane,
    uint32_t af[4][4], uint32_t bfr[4][4])
{
    int kc0 = ks * 2;
    #pragma unroll
    for (int am = 0; am < 4; am++) {
        int row = wm * 64 + am * 16 + (lane & 15);
        int kchunk = kc0 + (lane >> 4);
        uint32_t addr = aB + (uint32_t)(row * 128 + ((kchunk ^ (row & 7)) << 4));
        ldsm_x4(af[am][0], af[am][1], af[am][2], af[am][3], addr);
    }
    int rr = ks * 16 + (lane & 15);
    #pragma unroll
    for (int bn = 0; bn < 4; bn++) {
        int cc = wn * 8 + bn * 2 + (lane >> 4);
        uint32_t pc = (uint32_t)((cc & 8) | ((cc & 7) ^ (rr & 7)));
        uint32_t addr = bB + (uint32_t)(rr * 256) + (pc << 4);
        ldsm_x4_t(bfr[bn][0], bfr[bn][1], bfr[bn][2], bfr[bn][3], addr);
    }
}

__global__ __launch_bounds__(128, 2)
void mma_gemm_kernel(const bf16* __restrict__ A, const bf16* __restrict__ A2,
                     const bf16* __restrict__ Bt,
                     const float* __restrict__ bias, float* __restrict__ outF,
                     bf16* __restrict__ outB, int M, int N, int Kd, int relu, int splitTT)
{
    extern __shared__ uint8_t dyn[];
    uint32_t sbase = smem_u32(dyn);
    int tid = threadIdx.x, lane = tid & 31, wid = tid >> 5;
    int wm = wid & 1, wn = wid >> 1;
    int m0 = blockIdx.y * 128, n0 = blockIdx.x * 128;
    const bf16* Ag;
    if (splitTT) {
        int b = m0 / TT, t0 = m0 % TT;
        Ag = (t0 < SS) ? A + ((long)(b * SS + t0)) * Kd
                       : A2 + ((long)(b * MM + (t0 - SS))) * Kd;
    } else {
        Ag = A + (long)m0 * Kd;
    }
    const bf16* Bg = Bt + n0;

    float acc[4][8][4];
    #pragma unroll
    for (int i = 0; i < 4; i++)
        #pragma unroll
        for (int j = 0; j < 8; j++)
            #pragma unroll
            for (int k = 0; k < 4; k++) acc[i][j][k] = 0.f;

    int NS = Kd / BKS;
    cp_stage(Ag, Bg, Kd, N, 0, sbase, tid);
    CP_COMMIT();
    if (NS > 1) {
        cp_stage(Ag, Bg, Kd, N, BKS, sbase + STG128, tid);
        CP_COMMIT();
    }

    uint32_t af[2][4][4], bfr[2][4][4];
    int buf = 0;
    for (int s = 0; s < NS; s++) {
        if (s + 1 < NS) { CP_WAIT(1); } else { CP_WAIT(0); }
        __syncthreads();
        if (s + 2 < NS) {
            cp_stage(Ag, Bg, Kd, N, (s + 2) * BKS,
                     sbase + (uint32_t)((buf + 2) % 3) * STG128, tid);
            CP_COMMIT();
        }

        uint32_t aB = sbase + (uint32_t)buf * STG128;
        uint32_t bB = aB + 16384u;
        load_frags(aB, bB, 0, wm, wn, lane, af[0], bfr[0]);
        #pragma unroll
        for (int ks = 0; ks < 4; ks++) {
            int cur = ks & 1;
            if (ks < 3)
                load_frags(aB, bB, ks + 1, wm, wn, lane, af[cur ^ 1], bfr[cur ^ 1]);
            #pragma unroll
            for (int am = 0; am < 4; am++)
                #pragma unroll
                for (int bn = 0; bn < 4; bn++) {
                    mma16816(acc[am][bn * 2 + 0], af[cur][am], bfr[cur][bn][0], bfr[cur][bn][1]);
                    mma16816(acc[am][bn * 2 + 1], af[cur][am], bfr[cur][bn][2], bfr[cur][bn][3]);
                }
        }
        buf = (buf + 1) % 3;
    }

    // epilogue: warp tile 64x64 at (wm*64, wn*64)
    int mbase = m0 + wm * 64 + (lane >> 2);
    int nbase = n0 + wn * 64 + (lane & 3) * 2;
    #pragma unroll
    for (int am = 0; am < 4; am++) {
        #pragma unroll
        for (int bo = 0; bo < 8; bo++) {
            int c = nbase + bo * 8;
            float b0v = 0.f, b1v = 0.f;
            if (bias) { b0v = __ldg(bias + c); b1v = __ldg(bias + c + 1); }
            float v0 = acc[am][bo][0] + b0v;
            float v1 = acc[am][bo][1] + b1v;
            float v2 = acc[am][bo][2] + b0v;
            float v3 = acc[am][bo][3] + b1v;
            if (relu) {
                v0 = fmaxf(v0, 0.f); v1 = fmaxf(v1, 0.f);
                v2 = fmaxf(v2, 0.f); v3 = fmaxf(v3, 0.f);
            }
            int r0 = mbase + am * 16;
            int r1 = r0 + 8;
            if (outF) {
                *(float2*)(outF + (long)r0 * N + c) = make_float2(v0, v1);
                *(float2*)(outF + (long)r1 * N + c) = make_float2(v2, v3);
            } else {
                __nv_bfloat162 p0 = __floats2bfloat162_rn(v0, v1);
                __nv_bfloat162 p1 = __floats2bfloat162_rn(v2, v3);
                *(__nv_bfloat162*)(outB + (long)r0 * N + c) = p0;
                *(__nv_bfloat162*)(outB + (long)r1 * N + c) = p1;
            }
        }
    }
}

// ---------------- tensor-core flash attention (K|V fused input) ----------------
#define FA_SMEM (8192 + 2*8192 + 2*8192)
__global__ __launch_bounds__(128)
void fa_kernel(const bf16* __restrict__ Q, const bf16* __restrict__ KV,
               const bf16* __restrict__ Ppos, bf16* __restrict__ out)
{
    extern __shared__ uint8_t smemraw[];
    uint32_t sQ = smem_u32(smemraw);
    uint32_t sK = sQ + 8192;
    uint32_t sV = sK + 16384;
    int tid = threadIdx.x, lane = tid & 31, w = tid >> 5;
    int q0 = blockIdx.x * 64;
    int bk = blockIdx.y;
    int b = bk / KH, hh = bk % KH;

    const bf16* Qg = Q + ((long)(b * MM + q0)) * HH + hh * DD;
    const bf16* Kg = KV + ((long)(b * TT + q0)) * KVS + hh * DD;
    const bf16* Vg = Kg + HH;

    #pragma unroll
    for (int i = 0; i < 4; i++) {
        int idx = tid + i * 128;
        int r = idx >> 3, c = idx & 7;
        uint32_t so = (uint32_t)(r * 128 + ((c ^ (r & 7)) << 4));
        CP_ASYNC16(sQ + so, Qg + (long)r * HH + c * 8);
        CP_ASYNC16(sK + so, Kg + (long)r * KVS + c * 8);
        CP_ASYNC16(sV + so, Vg + (long)r * KVS + c * 8);
    }
    CP_COMMIT();

    float Sacc[8][4];
    float Oacc[8][4];
    #pragma unroll
    for (int i = 0; i < 8; i++)
        #pragma unroll
        for (int j = 0; j < 4; j++) Oacc[i][j] = 0.f;
    uint32_t qf[4][4];
    float mrun0 = -1e30f, mrun1 = -1e30f, lrun0 = 0.f, lrun1 = 0.f;

    int r0 = w * 16 + (lane >> 2);
    const bf16* P0 = Ppos + ((long)((b * MM + q0 + r0)) * KH + hh) * SS;
    const bf16* P1 = Ppos + ((long)((b * MM + q0 + r0 + 8)) * KH + hh) * SS;

    for (int t = 0; t < 17; t++) {
        if (t + 1 < 17) {
            uint32_t dstK = sK + ((uint32_t)((t + 1) & 1)) * 8192u;
            uint32_t dstV = sV + ((uint32_t)((t + 1) & 1)) * 8192u;
            const bf16* Kt = Kg + (long)(t + 1) * 64 * KVS;
            const bf16* Vt = Vg + (long)(t + 1) * 64 * KVS;
            #pragma unroll
            for (int i = 0; i < 4; i++) {
                int idx = tid + i * 128;
                int r = idx >> 3, c = idx & 7;
                uint32_t so = (uint32_t)(r * 128 + ((c ^ (r & 7)) << 4));
                CP_ASYNC16(dstK + so, Kt + (long)r * KVS + c * 8);
                CP_ASYNC16(dstV + so, Vt + (long)r * KVS + c * 8);
            }
            CP_COMMIT();
            CP_WAIT(1);
        } else {
            CP_WAIT(0);
        }
        __syncthreads();

        if (t == 0) {
            #pragma unroll
            for (int kt = 0; kt < 4; kt++) {
                int rr = w * 16 + (lane & 15);
                int cc = kt * 2 + (lane >> 4);
                uint32_t addr = sQ + (uint32_t)(rr * 128 + ((cc ^ (rr & 7)) << 4));
                ldsm_x4(qf[kt][0], qf[kt][1], qf[kt][2], qf[kt][3], addr);
            }
        }
        uint32_t kb = sK + ((uint32_t)(t & 1)) * 8192u;
        uint32_t vb = sV + ((uint32_t)(t & 1)) * 8192u;

        #pragma unroll
        for (int i = 0; i < 8; i++) {
            Sacc[i][0] = 0.f; Sacc[i][1] = 0.f; Sacc[i][2] = 0.f; Sacc[i][3] = 0.f;
        }
        #pragma unroll
        for (int kt = 0; kt < 4; kt++) {
            #pragma unroll
            for (int pp = 0; pp < 4; pp++) {
                int rr = pp * 16 + (lane & 15);
                int cc = kt * 2 + (lane >> 4);
                uint32_t addr = kb + (uint32_t)(rr * 128 + ((cc ^ (rr & 7)) << 4));
                uint32_t f0, f1, f2, f3;
                ldsm_x4(f0, f1, f2, f3, addr);
                mma16816(Sacc[2 * pp],     qf[kt], f0, f2);
                mma16816(Sacc[2 * pp + 1], qf[kt], f1, f3);
            }
        }

        float mx0 = -1e30f, mx1 = -1e30f;
        int ubase = t * 64 + (lane & 3) * 2;
        #pragma unroll
        for (int nb = 0; nb < 8; nb++) {
            int u = ubase + nb * 8;
            int j0 = u - r0;
            int j2 = j0 - 8;
            Sacc[nb][0] = (j0 >= 0 && j0 < SS)
                ? (Sacc[nb][0] + __bfloat162float(P0[j0])) * 0.125f : -1e30f;
            Sacc[nb][1] = (j0 + 1 >= 0 && j0 + 1 < SS)
                ? (Sacc[nb][1] + __bfloat162float(P0[j0 + 1])) * 0.125f : -1e30f;
            Sacc[nb][2] = (j2 >= 0 && j2 < SS)
                ? (Sacc[nb][2] + __bfloat162float(P1[j2])) * 0.125f : -1e30f;
            Sacc[nb][3] = (j2 + 1 >= 0 && j2 + 1 < SS)
                ? (Sacc[nb][3] + __bfloat162float(P1[j2 + 1])) * 0.125f : -1e30f;
            mx0 = fmaxf(mx0, fmaxf(Sacc[nb][0], Sacc[nb][1]));
            mx1 = fmaxf(mx1, fmaxf(Sacc[nb][2], Sacc[nb][3]));
        }
        mx0 = fmaxf(mx0, __shfl_xor_sync(0xffffffffu, mx0, 1));
        mx0 = fmaxf(mx0, __shfl_xor_sync(0xffffffffu, mx0, 2));
        mx1 = fmaxf(mx1, __shfl_xor_sync(0xffffffffu, mx1, 1));
        mx1 = fmaxf(mx1, __shfl_xor_sync(0xffffffffu, mx1, 2));
        float mn0 = fmaxf(mrun0, mx0), mn1 = fmaxf(mrun1, mx1);
        float a0 = __expf(mrun0 - mn0), a1 = __expf(mrun1 - mn1);
        float s0 = 0.f, s1 = 0.f;
        #pragma unroll
        for (int nb = 0; nb < 8; nb++) {
            Sacc[nb][0] = __expf(Sacc[nb][0] - mn0);
            Sacc[nb][1] = __expf(Sacc[nb][1] - mn0);
            Sacc[nb][2] = __expf(Sacc[nb][2] - mn1);
            Sacc[nb][3] = __expf(Sacc[nb][3] - mn1);
            s0 += Sacc[nb][0] + Sacc[nb][1];
            s1 += Sacc[nb][2] + Sacc[nb][3];
        }
        s0 += __shfl_xor_sync(0xffffffffu, s0, 1);
        s0 += __shfl_xor_sync(0xffffffffu, s0, 2);
        s1 += __shfl_xor_sync(0xffffffffu, s1, 1);
        s1 += __shfl_xor_sync(0xffffffffu, s1, 2);
        lrun0 = lrun0 * a0 + s0; lrun1 = lrun1 * a1 + s1;
        mrun0 = mn0; mrun1 = mn1;
        #pragma unroll
        for (int i = 0; i < 8; i++) {
            Oacc[i][0] *= a0; Oacc[i][1] *= a0;
            Oacc[i][2] *= a1; Oacc[i][3] *= a1;
        }

        #pragma unroll
        for (int pt = 0; pt < 4; pt++) {
            uint32_t pa[4];
            __nv_bfloat162 p0 = __floats2bfloat162_rn(Sacc[2 * pt][0], Sacc[2 * pt][1]);
            __nv_bfloat162 p1 = __floats2bfloat162_rn(Sacc[2 * pt][2], Sacc[2 * pt][3]);
            __nv_bfloat162 p2 = __floats2bfloat162_rn(Sacc[2 * pt + 1][0], Sacc[2 * pt + 1][1]);
            __nv_bfloat162 p3 = __floats2bfloat162_rn(Sacc[2 * pt + 1][2], Sacc[2 * pt + 1][3]);
            pa[0] = *(uint32_t*)&p0; pa[1] = *(uint32_t*)&p1;
            pa[2] = *(uint32_t*)&p2; pa[3] = *(uint32_t*)&p3;
            #pragma unroll
            for (int db = 0; db < 4; db++) {
                int rr = pt * 16 + (lane & 15);
                int cc = db * 2 + (lane >> 4);
                uint32_t addr = vb + (uint32_t)(rr * 128 + ((cc ^ (rr & 7)) << 4));
                uint32_t f0, f1, f2, f3;
                ldsm_x4_t(f0, f1, f2, f3, addr);
                mma16816(Oacc[2 * db],     pa, f0, f1);
                mma16816(Oacc[2 * db + 1], pa, f2, f3);
            }
        }
        __syncthreads();
    }

    float inv0 = 1.f / lrun0, inv1 = 1.f / lrun1;
    bf16* o0 = out + ((long)(b * MM + q0 + r0)) * HH + hh * DD + (lane & 3) * 2;
    bf16* o1 = out + ((long)(b * MM + q0 + r0 + 8)) * HH + hh * DD + (lane & 3) * 2;
    #pragma unroll
    for (int db = 0; db < 8; db++) {
        __nv_bfloat162 v0 = __floats2bfloat162_rn(Oacc[db][0] * inv0, Oacc[db][1] * inv0);
        __nv_bfloat162 v1 = __floats2bfloat162_rn(Oacc[db][2] * inv1, Oacc[db][3] * inv1);
        *(__nv_bfloat162*)(o0 + db * 8) = v0;
        *(__nv_bfloat162*)(o1 + db * 8) = v1;
    }
}

// ---------------- layernorm of (x + r): fp32 + bf16 out ----------------
__global__ __launch_bounds__(256)
void ln_kernel(const float* __restrict__ x, const float* __restrict__ r,
               const float* __restrict__ s, const float* __restrict__ bta,
               float* __restrict__ out, bf16* __restrict__ outb) {
    __shared__ float sh[32];
    int row = blockIdx.x, tid = threadIdx.x;
    const float* xp = x + (long)row * HH;
    const float* rp = r + (long)row * HH;
    float v0 = xp[tid] + rp[tid];
    float v1 = xp[tid + 256] + rp[tid + 256];
    float v2 = xp[tid + 512] + rp[tid + 512];
    float sum = blockReduceSum(v0 + v1 + v2, sh);
    float mu = sum * (1.f / HH);
    float d0 = v0 - mu, d1 = v1 - mu, d2 = v2 - mu;
    float var = blockReduceSum(d0 * d0 + d1 * d1 + d2 * d2, sh) * (1.f / HH);
    float rstd = rsqrtf(var + 1e-5f);
    float* op = out + (long)row * HH;
    bf16* ob = outb + (long)row * HH;
    float o0 = d0 * rstd * s[tid]       + bta[tid];
    float o1 = d1 * rstd * s[tid + 256] + bta[tid + 256];
    float o2 = d2 * rstd * s[tid + 512] + bta[tid + 512];
    op[tid] = o0; op[tid + 256] = o1; op[tid + 512] = o2;
    ob[tid] = __float2bfloat16_rn(o0);
    ob[tid + 256] = __float2bfloat16_rn(o1);
    ob[tid + 512] = __float2bfloat16_rn(o2);
}

// ---------------- log-softmax: bf16 logits -> fp32 out (one-pass max+sum) --------
__global__ __launch_bounds__(512)
void lsm_bf_kernel(const bf16* __restrict__ logits, float* __restrict__ out) {
    __shared__ float shm[32], shs[32];
    long row = blockIdx.x;
    const uint4* p = (const uint4*)(logits + row * (long)VV);
    int tid = threadIdx.x, lane = tid & 31, w = tid >> 5;
    const int n8 = VV / 8;
    float mx = -1e30f, sm = 0.f;
    for (int i = tid; i < n8; i += 512) {
        uint4 u = p[i];
        float2 a = __bfloat1622float2(*(__nv_bfloat162*)&u.x);
        float2 b = __bfloat1622float2(*(__nv_bfloat162*)&u.y);
        float2 c = __bfloat1622float2(*(__nv_bfloat162*)&u.z);
        float2 d = __bfloat1622float2(*(__nv_bfloat162*)&u.w);
        float m8 = fmaxf(fmaxf(fmaxf(a.x, a.y), fmaxf(b.x, b.y)),
                         fmaxf(fmaxf(c.x, c.y), fmaxf(d.x, d.y)));
        float s8 = __expf(a.x - m8) + __expf(a.y - m8) + __expf(b.x - m8) + __expf(b.y - m8)
                 + __expf(c.x - m8) + __expf(c.y - m8) + __expf(d.x - m8) + __expf(d.y - m8);
        float nm = fmaxf(mx, m8);
        sm = sm * __expf(mx - nm) + s8 * __expf(m8 - nm);
        mx = nm;
    }
    #pragma unroll
    for (int o = 16; o; o >>= 1) {
        float mo = __shfl_xor_sync(0xffffffffu, mx, o);
        float so = __shfl_xor_sync(0xffffffffu, sm, o);
        float nm = fmaxf(mx, mo);
        sm = sm * __expf(mx - nm) + so * __expf(mo - nm);
        mx = nm;
    }
    if (lane == 0) { shm[w] = mx; shs[w] = sm; }
    __syncthreads();
    if (w == 0) {
        mx = (lane < 16) ? shm[lane] : -1e30f;
        sm = (lane < 16) ? shs[lane] : 0.f;
        #pragma unroll
        for (int o = 8; o; o >>= 1) {
            float mo = __shfl_xor_sync(0xffffffffu, mx, o);
            float so = __shfl_xor_sync(0xffffffffu, sm, o);
            float nm = fmaxf(mx, mo);
            sm = sm * __expf(mx - nm) + so * __expf(mo - nm);
            mx = nm;
        }
        if (lane == 0) { shm[0] = mx; shs[0] = sm; }
    }
    __syncthreads();
    float lse = shm[0] + logf(shs[0]);
    float4* o = (float4*)(out + row * (long)VV);
    for (int i = tid; i < n8; i += 512) {
        uint4 u = p[i];
        float2 a = __bfloat1622float2(*(__nv_bfloat162*)&u.x);
        float2 b = __bfloat1622float2(*(__nv_bfloat162*)&u.y);
        float2 c = __bfloat1622float2(*(__nv_bfloat162*)&u.z);
        float2 d = __bfloat1622float2(*(__nv_bfloat162*)&u.w);
        o[2 * i]     = make_float4(a.x - lse, a.y - lse, b.x - lse, b.y - lse);
        o[2 * i + 1] = make_float4(c.x - lse, c.y - lse, d.x - lse, d.y - lse);
    }
}

// ---------------- host orchestration ----------------
static inline void tc_gemm(const bf16* A, const bf16* B, const float* bias,
                           float* outF, bf16* outB, int M, int N, int Kd, int relu) {
    dim3 grid(N / 128, M / 128);
    mma_gemm_kernel<<<grid, 128, GEMM_DSMEM>>>(A, nullptr, B, bias, outF, outB,
                                               M, N, Kd, relu, 0);
}
static inline void tc_gemm_split(const bf16* Acache, const bf16* Ah, const bf16* B,
                                 bf16* outB, int M, int N, int Kd) {
    dim3 grid(N / 128, M / 128);
    mma_gemm_kernel<<<grid, 128, GEMM_DSMEM>>>(Acache, Ah, B, nullptr, nullptr, outB,
                                               M, N, Kd, 0, 1);
}
static inline void conv_bf16(const float* src, bf16* dst, long nelem) {
    long n4 = nelem / 4;
    conv_bf16_kernel<<<(int)((n4 + 255) / 256), 256>>>(src, dst, n4);
}

extern "C" void kernel_launch(void* const* d_in, const int* in_sizes, int n_in,
                              void* d_out, int out_size) {
    const int*   x       = (const int*)  d_in[0];
    const float* h_cache = (const float*)d_in[1];
    const float* key_pe  = (const float*)d_in[2];
    const float* emb     = (const float*)d_in[3];
    const float* Wq      = (const float*)d_in[4];
    const float* Wk      = (const float*)d_in[5];
    const float* Wv      = (const float*)d_in[6];
    const float* Wo      = (const float*)d_in[7];
    const float* fc1_w   = (const float*)d_in[8];
    const float* fc1_b   = (const float*)d_in[9];
    const float* fc2_w   = (const float*)d_in[10];
    const float* fc2_b   = (const float*)d_in[11];
    const float* ln1_s   = (const float*)d_in[12];
    const float* ln1_b   = (const float*)d_in[13];
    const float* ln2_s   = (const float*)d_in[14];
    const float* ln2_b   = (const float*)d_in[15];
    const float* out_w   = (const float*)d_in[16];
    const float* out_b   = (const float*)d_in[17];
    float* out = (float*)d_out;

    float *h, *t2;
    bf16 *pposbf, *logbf, *cachebf;
    bf16 *hbf, *qbf, *kvbf, *aobf, *ffbf, *pet;
    bf16 *wq, *wkv, *wo, *wf1, *wf2, *wout;
    cudaGetSymbolAddress((void**)&h,      g_h);
    cudaGetSymbolAddress((void**)&t2,     g_t2);
    cudaGetSymbolAddress((void**)&pposbf, g_pposbf);
    cudaGetSymbolAddress((void**)&logbf,  g_logbf);
    cudaGetSymbolAddress((void**)&cachebf,g_cachebf);
    cudaGetSymbolAddress((void**)&hbf,    g_hbf);
    cudaGetSymbolAddress((void**)&qbf,    g_qbf);
    cudaGetSymbolAddress((void**)&kvbf,   g_kvbf);
    cudaGetSymbolAddress((void**)&aobf,   g_aobf);
    cudaGetSymbolAddress((void**)&ffbf,   g_ffbf);
    cudaGetSymbolAddress((void**)&pet,    g_pet);
    cudaGetSymbolAddress((void**)&wq,     g_wq);
    cudaGetSymbolAddress((void**)&wkv,    g_wkv);
    cudaGetSymbolAddress((void**)&wo,     g_wo);
    cudaGetSymbolAddress((void**)&wf1,    g_wf1);
    cudaGetSymbolAddress((void**)&wf2,    g_wf2);
    cudaGetSymbolAddress((void**)&wout,   g_wout);

    cudaFuncSetAttribute(mma_gemm_kernel, cudaFuncAttributeMaxDynamicSharedMemorySize, GEMM_DSMEM);
    cudaFuncSetAttribute(fa_kernel, cudaFuncAttributeMaxDynamicSharedMemorySize, FA_SMEM);

    const int rows = BB * MM;   // 4096
    const long hs = (long)HH * HH;
    const long fs = (long)HH * FFD;

    // ---- weight prep: pure fp32->bf16 conversion, natural [K][N] layout ----
    conv_bf16(Wq,    wq,   (long)NLAYERS * hs);
    conv_bf16(Wo,    wo,   (long)NLAYERS * hs);
    conv_bf16(fc1_w, wf1,  (long)NLAYERS * fs);
    conv_bf16(fc2_w, wf2,  (long)NLAYERS * fs);
    conv_bf16(out_w, wout, (long)HH * VV);
    conv_bf16(key_pe, pet, (long)DD * SS);
    conv_bf16(h_cache, cachebf, (long)NLAYERS * BB * SS * HH);
    {
        long total = (long)NLAYERS * HH * (KVS / 4);
        conv_kv_kernel<<<(int)((total + 255) / 256), 256>>>(Wk, Wv, wkv);
    }

    embed_kernel<<<rows, 256>>>(x, emb, h, hbf);

    for (int l = 0; l < NLAYERS; l++) {
        const long wofs = (long)l * hs;
        const bf16* cache_l = cachebf + (long)l * BB * SS * HH;

        tc_gemm(hbf, wq + wofs, nullptr, nullptr, qbf, rows, HH, HH, 0);
        tc_gemm_split(cache_l, hbf, wkv + (long)l * HH * KVS, kvbf, BB * TT, KVS, HH);

        tc_gemm(qbf, pet, nullptr, nullptr, pposbf, rows * KH, SS, DD, 0);

        fa_kernel<<<dim3(MM / 64, BB * KH), 128, FA_SMEM>>>(qbf, kvbf, pposbf, aobf);

        tc_gemm(aobf, wo + wofs, nullptr, t2, nullptr, rows, HH, HH, 0);
        ln_kernel<<<rows, 256>>>(h, t2, ln1_s + l * HH, ln1_b + l * HH, h, hbf);

        tc_gemm(hbf,  wf1 + (long)l * fs, fc1_b + (long)l * FFD, nullptr, ffbf, rows, FFD, HH, 1);
        tc_gemm(ffbf, wf2 + (long)l * fs, fc2_b + (long)l * HH,  t2, nullptr, rows, HH, FFD, 0);
        ln_kernel<<<rows, 256>>>(h, t2, ln2_s + l * HH, ln2_b + l * HH, h, hbf);
    }

    // vocab projection -> bf16 logits, then log-softmax -> fp32 out
    tc_gemm(hbf, wout, out_b, nullptr, logbf, rows, VV, HH, 0);
    lsm_bf_kernel<<<rows, 512>>>(logbf, out);
}

// round 16
// speedup vs baseline: 1.0246x; 1.0246x over previous
#include <cuda_runtime.h>
#include <cuda_bf16.h>
#include <cstdint>

// ---------------- problem constants ----------------
#define NLAYERS 4
#define BB 8
#define MM 512
#define SS 1024
#define HH 768
#define KH 12
#define DD 64
#define FFD 3072
#define VV 32000
#define TT 1536   // S + M
#define KVS (2*HH)   // fused K|V row stride

typedef __nv_bfloat16 bf16;

// ---------------- scratch (device globals; no runtime alloc) ----------------
__device__ float g_h  [BB*MM*HH];
__device__ float g_t2 [BB*MM*HH];

__device__ __align__(16) bf16 g_pposbf[(long)BB*MM*KH*SS];   // 100 MB
__device__ __align__(16) bf16 g_logbf [(long)BB*MM*VV];      // 262 MB bf16 logits

__device__ __align__(16) bf16 g_cachebf[(long)NLAYERS*BB*SS*HH]; // 48 MB bf16 cache
__device__ __align__(16) bf16 g_hbf   [BB*MM*HH];
__device__ __align__(16) bf16 g_qbf   [BB*MM*HH];
__device__ __align__(16) bf16 g_kvbf  [(long)BB*TT*KVS];
__device__ __align__(16) bf16 g_aobf  [BB*MM*HH];
__device__ __align__(16) bf16 g_ffbf  [BB*MM*FFD];
__device__ __align__(16) bf16 g_pet   [SS*DD];

// transposed bf16 weights [N][K]
__device__ __align__(16) bf16 g_wtq [NLAYERS*HH*HH];
__device__ __align__(16) bf16 g_wtkv[NLAYERS*2*HH*HH];
__device__ __align__(16) bf16 g_wto [NLAYERS*HH*HH];
__device__ __align__(16) bf16 g_wtf1[NLAYERS*FFD*HH];
__device__ __align__(16) bf16 g_wtf2[NLAYERS*HH*FFD];
__device__ __align__(16) bf16 g_wtout[(long)VV*HH];

// ---------------- small helpers ----------------
__device__ __forceinline__ uint32_t smem_u32(const void* p) {
    uint32_t a;
    asm("{ .reg .u64 t; cvta.to.shared.u64 t, %1; cvt.u32.u64 %0, t; }" : "=r"(a) : "l"(p));
    return a;
}
__device__ __forceinline__ void ldsm_x4(uint32_t& r0, uint32_t& r1, uint32_t& r2, uint32_t& r3,
                                        uint32_t addr) {
    asm volatile("ldmatrix.sync.aligned.m8n8.x4.shared.b16 {%0,%1,%2,%3}, [%4];"
                 : "=r"(r0), "=r"(r1), "=r"(r2), "=r"(r3) : "r"(addr));
}
__device__ __forceinline__ void ldsm_x4_t(uint32_t& r0, uint32_t& r1, uint32_t& r2, uint32_t& r3,
                                          uint32_t addr) {
    asm volatile("ldmatrix.sync.aligned.m8n8.x4.trans.shared.b16 {%0,%1,%2,%3}, [%4];"
                 : "=r"(r0), "=r"(r1), "=r"(r2), "=r"(r3) : "r"(addr));
}
__device__ __forceinline__ void mma16816(float* c, const uint32_t* a, uint32_t b0, uint32_t b1) {
    asm volatile("mma.sync.aligned.m16n8k16.row.col.f32.bf16.bf16.f32 "
                 "{%0,%1,%2,%3}, {%4,%5,%6,%7}, {%8,%9}, {%0,%1,%2,%3};"
                 : "+f"(c[0]), "+f"(c[1]), "+f"(c[2]), "+f"(c[3])
                 : "r"(a[0]), "r"(a[1]), "r"(a[2]), "r"(a[3]), "r"(b0), "r"(b1));
}
#define CP_ASYNC16(dst, src) \
    asm volatile("cp.async.cg.shared.global [%0], [%1], 16;" :: "r"(dst), "l"(src))
#define CP_COMMIT() asm volatile("cp.async.commit_group;" ::: "memory")
#define CP_WAIT(N)  asm volatile("cp.async.wait_group %0;" :: "n"(N) : "memory")

// ---------------- reduction helpers ----------------
__device__ __forceinline__ float blockReduceSum(float v, float* sh) {
    __syncthreads();
    int lane = threadIdx.x & 31, w = threadIdx.x >> 5;
    #pragma unroll
    for (int o = 16; o; o >>= 1) v += __shfl_xor_sync(0xffffffffu, v, o);
    if (lane == 0) sh[w] = v;
    __syncthreads();
    int nw = (blockDim.x + 31) >> 5;
    v = (threadIdx.x < nw) ? sh[threadIdx.x] : 0.f;
    if (w == 0) {
        #pragma unroll
        for (int o = 16; o; o >>= 1) v += __shfl_xor_sync(0xffffffffu, v, o);
        if (lane == 0) sh[0] = v;
    }
    __syncthreads();
    return sh[0];
}

// ---------------- weight transpose + fp32->bf16 : W[K][N] -> Wt[N][K] ----------------
__global__ __launch_bounds__(256)
void transpose_kernel(const float* __restrict__ W, bf16* __restrict__ Wt, int Kd, int N,
                      long wstride, long wtstride) {
    __shared__ float t[64][33];
    const float* Wz = W + (long)blockIdx.z * wstride;
    bf16* Wtz = Wt + (long)blockIdx.z * wtstride;
    int tx = threadIdx.x, ty = threadIdx.y;
    int n0 = blockIdx.x * 32;
    int k0 = blockIdx.y * 64;
    #pragma unroll
    for (int i = 0; i < 8; i++) {
        int ky = i * 8 + ty;
        t[ky][tx] = Wz[(long)(k0 + ky) * N + n0 + tx];
    }
    __syncthreads();
    #pragma unroll
    for (int i = 0; i < 4; i++) {
        int n = i * 8 + ty;
        __nv_bfloat162 pk = __floats2bfloat162_rn(t[2 * tx][n], t[2 * tx + 1][n]);
        *(__nv_bfloat162*)(Wtz + (long)(n0 + n) * Kd + k0 + 2 * tx) = pk;
    }
}

// ---------------- one-time cache fp32 -> bf16 (all layers) ----------------
__global__ __launch_bounds__(256)
void conv_cache_kernel(const float* __restrict__ src, bf16* __restrict__ dst, long n4) {
    long i = (long)blockIdx.x * blockDim.x + threadIdx.x;
    if (i >= n4) return;
    float4 v = ((const float4*)src)[i];
    __nv_bfloat162 p0 = __floats2bfloat162_rn(v.x, v.y);
    __nv_bfloat162 p1 = __floats2bfloat162_rn(v.z, v.w);
    uint2 pk;
    pk.x = *(uint32_t*)&p0;
    pk.y = *(uint32_t*)&p1;
    ((uint2*)dst)[i] = pk;
}

// ---------------- embedding (fp32 + bf16) ----------------
__global__ void embed_kernel(const int* __restrict__ x, const float* __restrict__ emb,
                             float* __restrict__ h, bf16* __restrict__ hbf) {
    int row = blockIdx.x;
    int tok = x[row];
    const float* e = emb + (long)tok * HH;
    float* hp = h + (long)row * HH;
    bf16* hb = hbf + (long)row * HH;
    for (int i = threadIdx.x; i < HH; i += blockDim.x) {
        float v = e[i];
        hp[i] = v;
        hb[i] = __float2bfloat16_rn(v);
    }
}

// ================= GEMM: 128x128x64 tile, 4 warps (2m x 2n), warp tile 64x64 ======
// 3-stage cp.async pipeline + register-fragment double buffering.
#define BKS 64
#define STG128 32768u
#define GEMM_DSMEM (3 * 32768)

__device__ __forceinline__ void cp_stage(
    const bf16* __restrict__ Ag, const bf16* __restrict__ Bg,
    int Kd, int koff, uint32_t st, int tid)
{
    #pragma unroll
    for (int i = 0; i < 8; i++) {
        int id = tid + i * 128;
        int r = id >> 3, c = id & 7;
        uint32_t off = (uint32_t)(r * 128 + ((c ^ (r & 7)) << 4));
        CP_ASYNC16(st + off, Ag + (long)r * Kd + koff + c * 8);
        CP_ASYNC16(st + 16384u + off, Bg + (long)r * Kd + koff + c * 8);
    }
}

__device__ __forceinline__ void load_frags(
    uint32_t aB, uint32_t bB, int ks, int wm, int wn, int lane,
    uint32_t af[4][4], uint32_t bfr[4][4])
{
    int kc0 = ks * 2;
    #pragma unroll
    for (int am = 0; am < 4; am++) {
        int row = wm * 64 + am * 16 + (lane & 15);
        int kchunk = kc0 + (lane >> 4);
        uint32_t addr = aB + (uint32_t)(row * 128 + ((kchunk ^ (row & 7)) << 4));
        ldsm_x4(af[am][0], af[am][1], af[am][2], af[am][3], addr);
    }
    #pragma unroll
    for (int bn = 0; bn < 4; bn++) {
        int row = wn * 64 + bn * 16 + (lane & 7) + ((lane >> 4) << 3);
        int kchunk = kc0 + ((lane >> 3) & 1);
        uint32_t addr = bB + (uint32_t)(row * 128 + ((kchunk ^ (row & 7)) << 4));
        ldsm_x4(bfr[bn][0], bfr[bn][1], bfr[bn][2], bfr[bn][3], addr);
    }
}

__global__ __launch_bounds__(128, 2)
void mma_gemm_kernel(const bf16* __restrict__ A, const bf16* __restrict__ A2,
                     const bf16* __restrict__ Bt,
                     const float* __restrict__ bias, float* __restrict__ outF,
                     bf16* __restrict__ outB, int M, int N, int Kd, int relu, int splitTT)
{
    extern __shared__ uint8_t dyn[];
    uint32_t sbase = smem_u32(dyn);
    int tid = threadIdx.x, lane = tid & 31, wid = tid >> 5;
    int wm = wid & 1, wn = wid >> 1;
    int m0 = blockIdx.y * 128, n0 = blockIdx.x * 128;
    const bf16* Ag;
    if (splitTT) {
        int b = m0 / TT, t0 = m0 % TT;
        Ag = (t0 < SS) ? A + ((long)(b * SS + t0)) * Kd
                       : A2 + ((long)(b * MM + (t0 - SS))) * Kd;
    } else {
        Ag = A + (long)m0 * Kd;
    }
    const bf16* Bg = Bt + (long)n0 * Kd;

    float acc[4][8][4];
    #pragma unroll
    for (int i = 0; i < 4; i++)
        #pragma unroll
        for (int j = 0; j < 8; j++)
            #pragma unroll
            for (int k = 0; k < 4; k++) acc[i][j][k] = 0.f;

    int NS = Kd / BKS;
    cp_stage(Ag, Bg, Kd, 0, sbase, tid);
    CP_COMMIT();
    if (NS > 1) {
        cp_stage(Ag, Bg, Kd, BKS, sbase + STG128, tid);
        CP_COMMIT();
    }

    uint32_t af[2][4][4], bfr[2][4][4];
    int buf = 0;
    for (int s = 0; s < NS; s++) {
        if (s + 1 < NS) { CP_WAIT(1); } else { CP_WAIT(0); }
        __syncthreads();
        if (s + 2 < NS) {
            cp_stage(Ag, Bg, Kd, (s + 2) * BKS,
                     sbase + (uint32_t)((buf + 2) % 3) * STG128, tid);
            CP_COMMIT();
        }

        uint32_t aB = sbase + (uint32_t)buf * STG128;
        uint32_t bB = aB + 16384u;
        load_frags(aB, bB, 0, wm, wn, lane, af[0], bfr[0]);
        #pragma unroll
        for (int ks = 0; ks < 4; ks++) {
            int cur = ks & 1;
            if (ks < 3)
                load_frags(aB, bB, ks + 1, wm, wn, lane, af[cur ^ 1], bfr[cur ^ 1]);
            #pragma unroll
            for (int am = 0; am < 4; am++)
                #pragma unroll
                for (int bn = 0; bn < 4; bn++) {
                    mma16816(acc[am][bn * 2 + 0], af[cur][am], bfr[cur][bn][0], bfr[cur][bn][1]);
                    mma16816(acc[am][bn * 2 + 1], af[cur][am], bfr[cur][bn][2], bfr[cur][bn][3]);
                }
        }
        buf = (buf + 1) % 3;
    }

    // epilogue: warp tile 64x64 at (wm*64, wn*64)
    int mbase = m0 + wm * 64 + (lane >> 2);
    int nbase = n0 + wn * 64 + (lane & 3) * 2;
    #pragma unroll
    for (int am = 0; am < 4; am++) {
        #pragma unroll
        for (int bo = 0; bo < 8; bo++) {
            int c = nbase + bo * 8;
            float b0v = 0.f, b1v = 0.f;
            if (bias) { b0v = __ldg(bias + c); b1v = __ldg(bias + c + 1); }
            float v0 = acc[am][bo][0] + b0v;
            float v1 = acc[am][bo][1] + b1v;
            float v2 = acc[am][bo][2] + b0v;
            float v3 = acc[am][bo][3] + b1v;
            if (relu) {
                v0 = fmaxf(v0, 0.f); v1 = fmaxf(v1, 0.f);
                v2 = fmaxf(v2, 0.f); v3 = fmaxf(v3, 0.f);
            }
            int r0 = mbase + am * 16;
            int r1 = r0 + 8;
            if (outF) {
                *(float2*)(outF + (long)r0 * N + c) = make_float2(v0, v1);
                *(float2*)(outF + (long)r1 * N + c) = make_float2(v2, v3);
            } else {
                __nv_bfloat162 p0 = __floats2bfloat162_rn(v0, v1);
                __nv_bfloat162 p1 = __floats2bfloat162_rn(v2, v3);
                *(__nv_bfloat162*)(outB + (long)r0 * N + c) = p0;
                *(__nv_bfloat162*)(outB + (long)r1 * N + c) = p1;
            }
        }
    }
}

// ---------------- tensor-core flash attention (K|V fused input) ----------------
#define FA_SMEM (8192 + 2*8192 + 2*8192)
__global__ __launch_bounds__(128)
void fa_kernel(const bf16* __restrict__ Q, const bf16* __restrict__ KV,
               const bf16* __restrict__ Ppos, bf16* __restrict__ out)
{
    extern __shared__ uint8_t smemraw[];
    uint32_t sQ = smem_u32(smemraw);
    uint32_t sK = sQ + 8192;
    uint32_t sV = sK + 16384;
    int tid = threadIdx.x, lane = tid & 31, w = tid >> 5;
    int q0 = blockIdx.x * 64;
    int bk = blockIdx.y;
    int b = bk / KH, hh = bk % KH;

    const bf16* Qg = Q + ((long)(b * MM + q0)) * HH + hh * DD;
    const bf16* Kg = KV + ((long)(b * TT + q0)) * KVS + hh * DD;
    const bf16* Vg = Kg + HH;

    #pragma unroll
    for (int i = 0; i < 4; i++) {
        int idx = tid + i * 128;
        int r = idx >> 3, c = idx & 7;
        uint32_t so = (uint32_t)(r * 128 + ((c ^ (r & 7)) << 4));
        CP_ASYNC16(sQ + so, Qg + (long)r * HH + c * 8);
        CP_ASYNC16(sK + so, Kg + (long)r * KVS + c * 8);
        CP_ASYNC16(sV + so, Vg + (long)r * KVS + c * 8);
    }
    CP_COMMIT();

    float Sacc[8][4];
    float Oacc[8][4];
    #pragma unroll
    for (int i = 0; i < 8; i++)
        #pragma unroll
        for (int j = 0; j < 4; j++) Oacc[i][j] = 0.f;
    uint32_t qf[4][4];
    float mrun0 = -1e30f, mrun1 = -1e30f, lrun0 = 0.f, lrun1 = 0.f;

    int r0 = w * 16 + (lane >> 2);
    const bf16* P0 = Ppos + ((long)((b * MM + q0 + r0)) * KH + hh) * SS;
    const bf16* P1 = Ppos + ((long)((b * MM + q0 + r0 + 8)) * KH + hh) * SS;

    for (int t = 0; t < 17; t++) {
        if (t + 1 < 17) {
            uint32_t dstK = sK + ((uint32_t)((t + 1) & 1)) * 8192u;
            uint32_t dstV = sV + ((uint32_t)((t + 1) & 1)) * 8192u;
            const bf16* Kt = Kg + (long)(t + 1) * 64 * KVS;
            const bf16* Vt = Vg + (long)(t + 1) * 64 * KVS;
            #pragma unroll
            for (int i = 0; i < 4; i++) {
                int idx = tid + i * 128;
                int r = idx >> 3, c = idx & 7;
                uint32_t so = (uint32_t)(r * 128 + ((c ^ (r & 7)) << 4));
                CP_ASYNC16(dstK + so, Kt + (long)r * KVS + c * 8);
                CP_ASYNC16(dstV + so, Vt + (long)r * KVS + c * 8);
            }
            CP_COMMIT();
            CP_WAIT(1);
        } else {
            CP_WAIT(0);
        }
        __syncthreads();

        if (t == 0) {
            #pragma unroll
            for (int kt = 0; kt < 4; kt++) {
                int rr = w * 16 + (lane & 15);
                int cc = kt * 2 + (lane >> 4);
                uint32_t addr = sQ + (uint32_t)(rr * 128 + ((cc ^ (rr & 7)) << 4));
                ldsm_x4(qf[kt][0], qf[kt][1], qf[kt][2], qf[kt][3], addr);
            }
        }
        uint32_t kb = sK + ((uint32_t)(t & 1)) * 8192u;
        uint32_t vb = sV + ((uint32_t)(t & 1)) * 8192u;

        #pragma unroll
        for (int i = 0; i < 8; i++) {
            Sacc[i][0] = 0.f; Sacc[i][1] = 0.f; Sacc[i][2] = 0.f; Sacc[i][3] = 0.f;
        }
        #pragma unroll
        for (int kt = 0; kt < 4; kt++) {
            #pragma unroll
            for (int pp = 0; pp < 4; pp++) {
                int rr = pp * 16 + (lane & 15);
                int cc = kt * 2 + (lane >> 4);
                uint32_t addr = kb + (uint32_t)(rr * 128 + ((cc ^ (rr & 7)) << 4));
                uint32_t f0, f1, f2, f3;
                ldsm_x4(f0, f1, f2, f3, addr);
                mma16816(Sacc[2 * pp],     qf[kt], f0, f2);
                mma16816(Sacc[2 * pp + 1], qf[kt], f1, f3);
            }
        }

        float mx0 = -1e30f, mx1 = -1e30f;
        int ubase = t * 64 + (lane & 3) * 2;
        #pragma unroll
        for (int nb = 0; nb < 8; nb++) {
            int u = ubase + nb * 8;
            int j0 = u - r0;
            int j2 = j0 - 8;
            Sacc[nb][0] = (j0 >= 0 && j0 < SS)
                ? (Sacc[nb][0] + __bfloat162float(P0[j0])) * 0.125f : -1e30f;
            Sacc[nb][1] = (j0 + 1 >= 0 && j0 + 1 < SS)
                ? (Sacc[nb][1] + __bfloat162float(P0[j0 + 1])) * 0.125f : -1e30f;
            Sacc[nb][2] = (j2 >= 0 && j2 < SS)
                ? (Sacc[nb][2] + __bfloat162float(P1[j2])) * 0.125f : -1e30f;
            Sacc[nb][3] = (j2 + 1 >= 0 && j2 + 1 < SS)
                ? (Sacc[nb][3] + __bfloat162float(P1[j2 + 1])) * 0.125f : -1e30f;
            mx0 = fmaxf(mx0, fmaxf(Sacc[nb][0], Sacc[nb][1]));
            mx1 = fmaxf(mx1, fmaxf(Sacc[nb][2], Sacc[nb][3]));
        }
        mx0 = fmaxf(mx0, __shfl_xor_sync(0xffffffffu, mx0, 1));
        mx0 = fmaxf(mx0, __shfl_xor_sync(0xffffffffu, mx0, 2));
        mx1 = fmaxf(mx1, __shfl_xor_sync(0xffffffffu, mx1, 1));
        mx1 = fmaxf(mx1, __shfl_xor_sync(0xffffffffu, mx1, 2));
        float mn0 = fmaxf(mrun0, mx0), mn1 = fmaxf(mrun1, mx1);
        float a0 = __expf(mrun0 - mn0), a1 = __expf(mrun1 - mn1);
        float s0 = 0.f, s1 = 0.f;
        #pragma unroll
        for (int nb = 0; nb < 8; nb++) {
            Sacc[nb][0] = __expf(Sacc[nb][0] - mn0);
            Sacc[nb][1] = __expf(Sacc[nb][1] - mn0);
            Sacc[nb][2] = __expf(Sacc[nb][2] - mn1);
            Sacc[nb][3] = __expf(Sacc[nb][3] - mn1);
            s0 += Sacc[nb][0] + Sacc[nb][1];
            s1 += Sacc[nb][2] + Sacc[nb][3];
        }
        s0 += __shfl_xor_sync(0xffffffffu, s0, 1);
        s0 += __shfl_xor_sync(0xffffffffu, s0, 2);
        s1 += __shfl_xor_sync(0xffffffffu, s1, 1);
        s1 += __shfl_xor_sync(0xffffffffu, s1, 2);
        lrun0 = lrun0 * a0 + s0; lrun1 = lrun1 * a1 + s1;
        mrun0 = mn0; mrun1 = mn1;
        #pragma unroll
        for (int i = 0; i < 8; i++) {
            Oacc[i][0] *= a0; Oacc[i][1] *= a0;
            Oacc[i][2] *= a1; Oacc[i][3] *= a1;
        }

        #pragma unroll
        for (int pt = 0; pt < 4; pt++) {
            uint32_t pa[4];
            __nv_bfloat162 p0 = __floats2bfloat162_rn(Sacc[2 * pt][0], Sacc[2 * pt][1]);
            __nv_bfloat162 p1 = __floats2bfloat162_rn(Sacc[2 * pt][2], Sacc[2 * pt][3]);
            __nv_bfloat162 p2 = __floats2bfloat162_rn(Sacc[2 * pt + 1][0], Sacc[2 * pt + 1][1]);
            __nv_bfloat162 p3 = __floats2bfloat162_rn(Sacc[2 * pt + 1][2], Sacc[2 * pt + 1][3]);
            pa[0] = *(uint32_t*)&p0; pa[1] = *(uint32_t*)&p1;
            pa[2] = *(uint32_t*)&p2; pa[3] = *(uint32_t*)&p3;
            #pragma unroll
            for (int db = 0; db < 4; db++) {
                int rr = pt * 16 + (lane & 15);
                int cc = db * 2 + (lane >> 4);
                uint32_t addr = vb + (uint32_t)(rr * 128 + ((cc ^ (rr & 7)) << 4));
                uint32_t f0, f1, f2, f3;
                ldsm_x4_t(f0, f1, f2, f3, addr);
                mma16816(Oacc[2 * db],     pa, f0, f1);
                mma16816(Oacc[2 * db + 1], pa, f2, f3);
            }
        }
        __syncthreads();
    }

    float inv0 = 1.f / lrun0, inv1 = 1.f / lrun1;
    bf16* o0 = out + ((long)(b * MM + q0 + r0)) * HH + hh * DD + (lane & 3) * 2;
    bf16* o1 = out + ((long)(b * MM + q0 + r0 + 8)) * HH + hh * DD + (lane & 3) * 2;
    #pragma unroll
    for (int db = 0; db < 8; db++) {
        __nv_bfloat162 v0 = __floats2bfloat162_rn(Oacc[db][0] * inv0, Oacc[db][1] * inv0);
        __nv_bfloat162 v1 = __floats2bfloat162_rn(Oacc[db][2] * inv1, Oacc[db][3] * inv1);
        *(__nv_bfloat162*)(o0 + db * 8) = v0;
        *(__nv_bfloat162*)(o1 + db * 8) = v1;
    }
}

// ---------------- layernorm of (x + r): fp32 + bf16 out ----------------
__global__ __launch_bounds__(256)
void ln_kernel(const float* __restrict__ x, const float* __restrict__ r,
               const float* __restrict__ s, const float* __restrict__ bta,
               float* __restrict__ out, bf16* __restrict__ outb) {
    __shared__ float sh[32];
    int row = blockIdx.x, tid = threadIdx.x;
    const float* xp = x + (long)row * HH;
    const float* rp = r + (long)row * HH;
    float v0 = xp[tid] + rp[tid];
    float v1 = xp[tid + 256] + rp[tid + 256];
    float v2 = xp[tid + 512] + rp[tid + 512];
    float sum = blockReduceSum(v0 + v1 + v2, sh);
    float mu = sum * (1.f / HH);
    float d0 = v0 - mu, d1 = v1 - mu, d2 = v2 - mu;
    float var = blockReduceSum(d0 * d0 + d1 * d1 + d2 * d2, sh) * (1.f / HH);
    float rstd = rsqrtf(var + 1e-5f);
    float* op = out + (long)row * HH;
    bf16* ob = outb + (long)row * HH;
    float o0 = d0 * rstd * s[tid]       + bta[tid];
    float o1 = d1 * rstd * s[tid + 256] + bta[tid + 256];
    float o2 = d2 * rstd * s[tid + 512] + bta[tid + 512];
    op[tid] = o0; op[tid + 256] = o1; op[tid + 512] = o2;
    ob[tid] = __float2bfloat16_rn(o0);
    ob[tid + 256] = __float2bfloat16_rn(o1);
    ob[tid + 512] = __float2bfloat16_rn(o2);
}

// ---------------- log-softmax: bf16 logits -> fp32 out, row cached in smem ------
#define LSM_SMEM (VV * 2)   // 64000 bytes: one bf16 row
__global__ __launch_bounds__(512)
void lsm_bf_kernel(const bf16* __restrict__ logits, float* __restrict__ out) {
    extern __shared__ uint8_t lsmemraw[];
    uint4* rowc = (uint4*)lsmemraw;
    __shared__ float shm[32], shs[32];
    long row = blockIdx.x;
    const uint4* p = (const uint4*)(logits + row * (long)VV);
    int tid = threadIdx.x, lane = tid & 31, w = tid >> 5;
    const int n8 = VV / 8;
    float mx = -1e30f, sm = 0.f;
    for (int i = tid; i < n8; i += 512) {
        uint4 u = p[i];
        rowc[i] = u;
        float2 a = __bfloat1622float2(*(__nv_bfloat162*)&u.x);
        float2 b = __bfloat1622float2(*(__nv_bfloat162*)&u.y);
        float2 c = __bfloat1622float2(*(__nv_bfloat162*)&u.z);
        float2 d = __bfloat1622float2(*(__nv_bfloat162*)&u.w);
        float m8 = fmaxf(fmaxf(fmaxf(a.x, a.y), fmaxf(b.x, b.y)),
                         fmaxf(fmaxf(c.x, c.y), fmaxf(d.x, d.y)));
        float s8 = __expf(a.x - m8) + __expf(a.y - m8) + __expf(b.x - m8) + __expf(b.y - m8)
                 + __expf(c.x - m8) + __expf(c.y - m8) + __expf(d.x - m8) + __expf(d.y - m8);
        float nm = fmaxf(mx, m8);
        sm = sm * __expf(mx - nm) + s8 * __expf(m8 - nm);
        mx = nm;
    }
    #pragma unroll
    for (int o = 16; o; o >>= 1) {
        float mo = __shfl_xor_sync(0xffffffffu, mx, o);
        float so = __shfl_xor_sync(0xffffffffu, sm, o);
        float nm = fmaxf(mx, mo);
        sm = sm * __expf(mx - nm) + so * __expf(mo - nm);
        mx = nm;
    }
    if (lane == 0) { shm[w] = mx; shs[w] = sm; }
    __syncthreads();
    if (w == 0) {
        mx = (lane < 16) ? shm[lane] : -1e30f;
        sm = (lane < 16) ? shs[lane] : 0.f;
        #pragma unroll
        for (int o = 8; o; o >>= 1) {
            float mo = __shfl_xor_sync(0xffffffffu, mx, o);
            float so = __shfl_xor_sync(0xffffffffu, sm, o);
            float nm = fmaxf(mx, mo);
            sm = sm * __expf(mx - nm) + so * __expf(mo - nm);
            mx = nm;
        }
        if (lane == 0) { shm[0] = mx; shs[0] = sm; }
    }
    __syncthreads();
    float lse = shm[0] + logf(shs[0]);
    float4* o = (float4*)(out + row * (long)VV);
    for (int i = tid; i < n8; i += 512) {
        uint4 u = rowc[i];
        float2 a = __bfloat1622float2(*(__nv_bfloat162*)&u.x);
        float2 b = __bfloat1622float2(*(__nv_bfloat162*)&u.y);
        float2 c = __bfloat1622float2(*(__nv_bfloat162*)&u.z);
        float2 d = __bfloat1622float2(*(__nv_bfloat162*)&u.w);
        o[2 * i]     = make_float4(a.x - lse, a.y - lse, b.x - lse, b.y - lse);
        o[2 * i + 1] = make_float4(c.x - lse, c.y - lse, d.x - lse, d.y - lse);
    }
}

// ---------------- host orchestration ----------------
static inline void tc_gemm(const bf16* A, const bf16* B, const float* bias,
                           float* outF, bf16* outB, int M, int N, int Kd, int relu) {
    dim3 grid(N / 128, M / 128);
    mma_gemm_kernel<<<grid, 128, GEMM_DSMEM>>>(A, nullptr, B, bias, outF, outB,
                                               M, N, Kd, relu, 0);
}
static inline void tc_gemm_split(const bf16* Acache, const bf16* Ah, const bf16* B,
                                 bf16* outB, int M, int N, int Kd) {
    dim3 grid(N / 128, M / 128);
    mma_gemm_kernel<<<grid, 128, GEMM_DSMEM>>>(Acache, Ah, B, nullptr, nullptr, outB,
                                               M, N, Kd, 0, 1);
}
static inline void transpose_w(const float* W, bf16* Wt, int Kd, int N,
                               int layers, long wstride, long wtstride) {
    dim3 grid(N / 32, Kd / 64, layers);
    transpose_kernel<<<grid, dim3(32, 8)>>>(W, Wt, Kd, N, wstride, wtstride);
}

extern "C" void kernel_launch(void* const* d_in, const int* in_sizes, int n_in,
                              void* d_out, int out_size) {
    const int*   x       = (const int*)  d_in[0];
    const float* h_cache = (const float*)d_in[1];
    const float* key_pe  = (const float*)d_in[2];
    const float* emb     = (const float*)d_in[3];
    const float* Wq      = (const float*)d_in[4];
    const float* Wk      = (const float*)d_in[5];
    const float* Wv      = (const float*)d_in[6];
    const float* Wo      = (const float*)d_in[7];
    const float* fc1_w   = (const float*)d_in[8];
    const float* fc1_b   = (const float*)d_in[9];
    const float* fc2_w   = (const float*)d_in[10];
    const float* fc2_b   = (const float*)d_in[11];
    const float* ln1_s   = (const float*)d_in[12];
    const float* ln1_b   = (const float*)d_in[13];
    const float* ln2_s   = (const float*)d_in[14];
    const float* ln2_b   = (const float*)d_in[15];
    const float* out_w   = (const float*)d_in[16];
    const float* out_b   = (const float*)d_in[17];
    float* out = (float*)d_out;

    float *h, *t2;
    bf16 *pposbf, *logbf, *cachebf;
    bf16 *hbf, *qbf, *kvbf, *aobf, *ffbf, *pet;
    bf16 *wtq, *wtkv, *wto, *wtf1, *wtf2, *wtout;
    cudaGetSymbolAddress((void**)&h,      g_h);
    cudaGetSymbolAddress((void**)&t2,     g_t2);
    cudaGetSymbolAddress((void**)&pposbf, g_pposbf);
    cudaGetSymbolAddress((void**)&logbf,  g_logbf);
    cudaGetSymbolAddress((void**)&cachebf,g_cachebf);
    cudaGetSymbolAddress((void**)&hbf,    g_hbf);
    cudaGetSymbolAddress((void**)&qbf,    g_qbf);
    cudaGetSymbolAddress((void**)&kvbf,   g_kvbf);
    cudaGetSymbolAddress((void**)&aobf,   g_aobf);
    cudaGetSymbolAddress((void**)&ffbf,   g_ffbf);
    cudaGetSymbolAddress((void**)&pet,    g_pet);
    cudaGetSymbolAddress((void**)&wtq,    g_wtq);
    cudaGetSymbolAddress((void**)&wtkv,   g_wtkv);
    cudaGetSymbolAddress((void**)&wto,    g_wto);
    cudaGetSymbolAddress((void**)&wtf1,   g_wtf1);
    cudaGetSymbolAddress((void**)&wtf2,   g_wtf2);
    cudaGetSymbolAddress((void**)&wtout,  g_wtout);

    cudaFuncSetAttribute(mma_gemm_kernel, cudaFuncAttributeMaxDynamicSharedMemorySize, GEMM_DSMEM);
    cudaFuncSetAttribute(fa_kernel, cudaFuncAttributeMaxDynamicSharedMemorySize, FA_SMEM);
    cudaFuncSetAttribute(lsm_bf_kernel, cudaFuncAttributeMaxDynamicSharedMemorySize, LSM_SMEM);

    const int rows = BB * MM;   // 4096
    const long hs = (long)HH * HH;
    const long fs = (long)HH * FFD;

    // ---- weight prep (batched over layers) + one-time cache conversion ----
    transpose_w(Wq, wtq, HH, HH, NLAYERS, hs, hs);
    transpose_w(Wk, wtkv,      HH, HH, NLAYERS, hs, 2 * hs);
    transpose_w(Wv, wtkv + hs, HH, HH, NLAYERS, hs, 2 * hs);
    transpose_w(Wo, wto, HH, HH, NLAYERS, hs, hs);
    transpose_w(fc1_w, wtf1, HH, FFD, NLAYERS, fs, fs);
    transpose_w(fc2_w, wtf2, FFD, HH, NLAYERS, fs, fs);
    transpose_w(out_w, wtout, HH, VV, 1, 0, 0);
    transpose_w(key_pe, pet, DD, SS, 1, 0, 0);
    {
        long n4 = (long)NLAYERS * BB * SS * HH / 4;
        conv_cache_kernel<<<(int)((n4 + 255) / 256), 256>>>(h_cache, cachebf, n4);
    }

    embed_kernel<<<rows, 256>>>(x, emb, h, hbf);

    for (int l = 0; l < NLAYERS; l++) {
        const long wo = (long)l * hs;
        const bf16* cache_l = cachebf + (long)l * BB * SS * HH;

        tc_gemm(hbf, wtq + wo, nullptr, nullptr, qbf, rows, HH, HH, 0);
        tc_gemm_split(cache_l, hbf, wtkv + (long)l * 2 * hs, kvbf, BB * TT, KVS, HH);

        tc_gemm(qbf, pet, nullptr, nullptr, pposbf, rows * KH, SS, DD, 0);

        fa_kernel<<<dim3(MM / 64, BB * KH), 128, FA_SMEM>>>(qbf, kvbf, pposbf, aobf);

        tc_gemm(aobf, wto + wo, nullptr, t2, nullptr, rows, HH, HH, 0);
        ln_kernel<<<rows, 256>>>(h, t2, ln1_s + l * HH, ln1_b + l * HH, h, hbf);

        tc_gemm(hbf,  wtf1 + (long)l * fs, fc1_b + (long)l * FFD, nullptr, ffbf, rows, FFD, HH, 1);
        tc_gemm(ffbf, wtf2 + (long)l * fs, fc2_b + (long)l * HH,  t2, nullptr, rows, HH, FFD, 0);
        ln_kernel<<<rows, 256>>>(h, t2, ln2_s + l * HH, ln2_b + l * HH, h, hbf);
    }

    // vocab projection -> bf16 logits, then log-softmax (row cached in smem)
    tc_gemm(hbf, wtout, out_b, nullptr, logbf, rows, VV, HH, 0);
    lsm_bf_kernel<<<rows, 512, LSM_SMEM>>>(logbf, out);
}

// round 17
// speedup vs baseline: 1.0403x; 1.0153x over previous
#include <cuda_runtime.h>
#include <cuda_bf16.h>
#include <cstdint>

// ---------------- problem constants ----------------
#define NLAYERS 4
#define BB 8
#define MM 512
#define SS 1024
#define HH 768
#define KH 12
#define DD 64
#define FFD 3072
#define VV 32000
#define TT 1536   // S + M
#define KVS (2*HH)   // fused K|V row stride

typedef __nv_bfloat16 bf16;

// ---------------- scratch (device globals; no runtime alloc) ----------------
__device__ float g_h  [BB*MM*HH];
__device__ float g_t2 [BB*MM*HH];

__device__ __align__(16) bf16 g_pposbf[(long)BB*MM*KH*SS];   // 100 MB
__device__ __align__(16) bf16 g_logbf [(long)BB*MM*VV];      // 262 MB bf16 logits

__device__ __align__(16) bf16 g_cachebf[(long)NLAYERS*BB*SS*HH]; // 48 MB bf16 cache
__device__ __align__(16) bf16 g_hbf   [BB*MM*HH];
__device__ __align__(16) bf16 g_qbf   [BB*MM*HH];
__device__ __align__(16) bf16 g_kvbf  [(long)BB*TT*KVS];
__device__ __align__(16) bf16 g_aobf  [BB*MM*HH];
__device__ __align__(16) bf16 g_ffbf  [BB*MM*FFD];
__device__ __align__(16) bf16 g_pet   [SS*DD];

// transposed bf16 weights [N][K]
__device__ __align__(16) bf16 g_wtq [NLAYERS*HH*HH];
__device__ __align__(16) bf16 g_wtkv[NLAYERS*2*HH*HH];
__device__ __align__(16) bf16 g_wto [NLAYERS*HH*HH];
__device__ __align__(16) bf16 g_wtf1[NLAYERS*FFD*HH];
__device__ __align__(16) bf16 g_wtf2[NLAYERS*HH*FFD];
__device__ __align__(16) bf16 g_wtout[(long)VV*HH];

// ---------------- small helpers ----------------
__device__ __forceinline__ uint32_t smem_u32(const void* p) {
    uint32_t a;
    asm("{ .reg .u64 t; cvta.to.shared.u64 t, %1; cvt.u32.u64 %0, t; }" : "=r"(a) : "l"(p));
    return a;
}
__device__ __forceinline__ void ldsm_x4(uint32_t& r0, uint32_t& r1, uint32_t& r2, uint32_t& r3,
                                        uint32_t addr) {
    asm volatile("ldmatrix.sync.aligned.m8n8.x4.shared.b16 {%0,%1,%2,%3}, [%4];"
                 : "=r"(r0), "=r"(r1), "=r"(r2), "=r"(r3) : "r"(addr));
}
__device__ __forceinline__ void ldsm_x4_t(uint32_t& r0, uint32_t& r1, uint32_t& r2, uint32_t& r3,
                                          uint32_t addr) {
    asm volatile("ldmatrix.sync.aligned.m8n8.x4.trans.shared.b16 {%0,%1,%2,%3}, [%4];"
                 : "=r"(r0), "=r"(r1), "=r"(r2), "=r"(r3) : "r"(addr));
}
__device__ __forceinline__ void mma16816(float* c, const uint32_t* a, uint32_t b0, uint32_t b1) {
    asm volatile("mma.sync.aligned.m16n8k16.row.col.f32.bf16.bf16.f32 "
                 "{%0,%1,%2,%3}, {%4,%5,%6,%7}, {%8,%9}, {%0,%1,%2,%3};"
                 : "+f"(c[0]), "+f"(c[1]), "+f"(c[2]), "+f"(c[3])
                 : "r"(a[0]), "r"(a[1]), "r"(a[2]), "r"(a[3]), "r"(b0), "r"(b1));
}
#define CP_ASYNC16(dst, src) \
    asm volatile("cp.async.cg.shared.global [%0], [%1], 16;" :: "r"(dst), "l"(src))
#define CP_COMMIT() asm volatile("cp.async.commit_group;" ::: "memory")
#define CP_WAIT(N)  asm volatile("cp.async.wait_group %0;" :: "n"(N) : "memory")

// ---------------- reduction helpers ----------------
__device__ __forceinline__ float blockReduceSum(float v, float* sh) {
    __syncthreads();
    int lane = threadIdx.x & 31, w = threadIdx.x >> 5;
    #pragma unroll
    for (int o = 16; o; o >>= 1) v += __shfl_xor_sync(0xffffffffu, v, o);
    if (lane == 0) sh[w] = v;
    __syncthreads();
    int nw = (blockDim.x + 31) >> 5;
    v = (threadIdx.x < nw) ? sh[threadIdx.x] : 0.f;
    if (w == 0) {
        #pragma unroll
        for (int o = 16; o; o >>= 1) v += __shfl_xor_sync(0xffffffffu, v, o);
        if (lane == 0) sh[0] = v;
    }
    __syncthreads();
    return sh[0];
}

// ---------------- weight transpose + fp32->bf16 : W[K][N] -> Wt[N][K] ----------------
__global__ __launch_bounds__(256)
void transpose_kernel(const float* __restrict__ W, bf16* __restrict__ Wt, int Kd, int N,
                      long wstride, long wtstride) {
    __shared__ float t[64][33];
    const float* Wz = W + (long)blockIdx.z * wstride;
    bf16* Wtz = Wt + (long)blockIdx.z * wtstride;
    int tx = threadIdx.x, ty = threadIdx.y;
    int n0 = blockIdx.x * 32;
    int k0 = blockIdx.y * 64;
    #pragma unroll
    for (int i = 0; i < 8; i++) {
        int ky = i * 8 + ty;
        t[ky][tx] = Wz[(long)(k0 + ky) * N + n0 + tx];
    }
    __syncthreads();
    #pragma unroll
    for (int i = 0; i < 4; i++) {
        int n = i * 8 + ty;
        __nv_bfloat162 pk = __floats2bfloat162_rn(t[2 * tx][n], t[2 * tx + 1][n]);
        *(__nv_bfloat162*)(Wtz + (long)(n0 + n) * Kd + k0 + 2 * tx) = pk;
    }
}

// ---------------- one-time cache fp32 -> bf16 (all layers) ----------------
__global__ __launch_bounds__(256)
void conv_cache_kernel(const float* __restrict__ src, bf16* __restrict__ dst, long n4) {
    long i = (long)blockIdx.x * blockDim.x + threadIdx.x;
    if (i >= n4) return;
    float4 v = ((const float4*)src)[i];
    __nv_bfloat162 p0 = __floats2bfloat162_rn(v.x, v.y);
    __nv_bfloat162 p1 = __floats2bfloat162_rn(v.z, v.w);
    uint2 pk;
    pk.x = *(uint32_t*)&p0;
    pk.y = *(uint32_t*)&p1;
    ((uint2*)dst)[i] = pk;
}

// ---------------- embedding (fp32 + bf16) ----------------
__global__ void embed_kernel(const int* __restrict__ x, const float* __restrict__ emb,
                             float* __restrict__ h, bf16* __restrict__ hbf) {
    int row = blockIdx.x;
    int tok = x[row];
    const float* e = emb + (long)tok * HH;
    float* hp = h + (long)row * HH;
    bf16* hb = hbf + (long)row * HH;
    for (int i = threadIdx.x; i < HH; i += blockDim.x) {
        float v = e[i];
        hp[i] = v;
        hb[i] = __float2bfloat16_rn(v);
    }
}

// ================= GEMM: 128x128x64 tile, 4 warps (2m x 2n), warp tile 64x64 ======
// 3-stage cp.async pipeline + register-fragment double buffering.
#define BKS 64
#define STG128 32768u
#define GEMM_DSMEM (3 * 32768)

__device__ __forceinline__ void cp_stage(
    const bf16* __restrict__ Ag, const bf16* __restrict__ Bg,
    int Kd, int koff, uint32_t st, int tid)
{
    #pragma unroll
    for (int i = 0; i < 8; i++) {
        int id = tid + i * 128;
        int r = id >> 3, c = id & 7;
        uint32_t off = (uint32_t)(r * 128 + ((c ^ (r & 7)) << 4));
        CP_ASYNC16(st + off, Ag + (long)r * Kd + koff + c * 8);
        CP_ASYNC16(st + 16384u + off, Bg + (long)r * Kd + koff + c * 8);
    }
}

__device__ __forceinline__ void load_frags(
    uint32_t aB, uint32_t bB, int ks, int wm, int wn, int lane,
    uint32_t af[4][4], uint32_t bfr[4][4])
{
    int kc0 = ks * 2;
    #pragma unroll
    for (int am = 0; am < 4; am++) {
        int row = wm * 64 + am * 16 + (lane & 15);
        int kchunk = kc0 + (lane >> 4);
        uint32_t addr = aB + (uint32_t)(row * 128 + ((kchunk ^ (row & 7)) << 4));
        ldsm_x4(af[am][0], af[am][1], af[am][2], af[am][3], addr);
    }
    #pragma unroll
    for (int bn = 0; bn < 4; bn++) {
        int row = wn * 64 + bn * 16 + (lane & 7) + ((lane >> 4) << 3);
        int kchunk = kc0 + ((lane >> 3) & 1);
        uint32_t addr = bB + (uint32_t)(row * 128 + ((kchunk ^ (row & 7)) << 4));
        ldsm_x4(bfr[bn][0], bfr[bn][1], bfr[bn][2], bfr[bn][3], addr);
    }
}

__device__ __forceinline__ void gemm_body(
    const bf16* __restrict__ Ag, const bf16* __restrict__ Bg,
    const float* __restrict__ bias, float* __restrict__ outF,
    bf16* __restrict__ outB, int N, int Kd, int relu,
    int m0, int n0, uint32_t sbase, int tid)
{
    int lane = tid & 31, wid = tid >> 5;
    int wm = wid & 1, wn = wid >> 1;

    float acc[4][8][4];
    #pragma unroll
    for (int i = 0; i < 4; i++)
        #pragma unroll
        for (int j = 0; j < 8; j++)
            #pragma unroll
            for (int k = 0; k < 4; k++) acc[i][j][k] = 0.f;

    int NS = Kd / BKS;
    cp_stage(Ag, Bg, Kd, 0, sbase, tid);
    CP_COMMIT();
    if (NS > 1) {
        cp_stage(Ag, Bg, Kd, BKS, sbase + STG128, tid);
        CP_COMMIT();
    }

    uint32_t af[2][4][4], bfr[2][4][4];
    int buf = 0;
    for (int s = 0; s < NS; s++) {
        if (s + 1 < NS) { CP_WAIT(1); } else { CP_WAIT(0); }
        __syncthreads();
        if (s + 2 < NS) {
            cp_stage(Ag, Bg, Kd, (s + 2) * BKS,
                     sbase + (uint32_t)((buf + 2) % 3) * STG128, tid);
            CP_COMMIT();
        }

        uint32_t aB = sbase + (uint32_t)buf * STG128;
        uint32_t bB = aB + 16384u;
        load_frags(aB, bB, 0, wm, wn, lane, af[0], bfr[0]);
        #pragma unroll
        for (int ks = 0; ks < 4; ks++) {
            int cur = ks & 1;
            if (ks < 3)
                load_frags(aB, bB, ks + 1, wm, wn, lane, af[cur ^ 1], bfr[cur ^ 1]);
            #pragma unroll
            for (int am = 0; am < 4; am++)
                #pragma unroll
                for (int bn = 0; bn < 4; bn++) {
                    mma16816(acc[am][bn * 2 + 0], af[cur][am], bfr[cur][bn][0], bfr[cur][bn][1]);
                    mma16816(acc[am][bn * 2 + 1], af[cur][am], bfr[cur][bn][2], bfr[cur][bn][3]);
                }
        }
        buf = (buf + 1) % 3;
    }

    // epilogue: warp tile 64x64 at (wm*64, wn*64)
    int mbase = m0 + wm * 64 + (lane >> 2);
    int nbase = n0 + wn * 64 + (lane & 3) * 2;
    #pragma unroll
    for (int am = 0; am < 4; am++) {
        #pragma unroll
        for (int bo = 0; bo < 8; bo++) {
            int c = nbase + bo * 8;
            float b0v = 0.f, b1v = 0.f;
            if (bias) { b0v = __ldg(bias + c); b1v = __ldg(bias + c + 1); }
            float v0 = acc[am][bo][0] + b0v;
            float v1 = acc[am][bo][1] + b1v;
            float v2 = acc[am][bo][2] + b0v;
            float v3 = acc[am][bo][3] + b1v;
            if (relu) {
                v0 = fmaxf(v0, 0.f); v1 = fmaxf(v1, 0.f);
                v2 = fmaxf(v2, 0.f); v3 = fmaxf(v3, 0.f);
            }
            int r0 = mbase + am * 16;
            int r1 = r0 + 8;
            if (outF) {
                *(float2*)(outF + (long)r0 * N + c) = make_float2(v0, v1);
                *(float2*)(outF + (long)r1 * N + c) = make_float2(v2, v3);
            } else {
                __nv_bfloat162 p0 = __floats2bfloat162_rn(v0, v1);
                __nv_bfloat162 p1 = __floats2bfloat162_rn(v2, v3);
                *(__nv_bfloat162*)(outB + (long)r0 * N + c) = p0;
                *(__nv_bfloat162*)(outB + (long)r1 * N + c) = p1;
            }
        }
    }
}

__global__ __launch_bounds__(128, 2)
void mma_gemm_kernel(const bf16* __restrict__ A, const bf16* __restrict__ A2,
                     const bf16* __restrict__ Bt,
                     const float* __restrict__ bias, float* __restrict__ outF,
                     bf16* __restrict__ outB, int M, int N, int Kd, int relu, int splitTT)
{
    extern __shared__ uint8_t dyn[];
    uint32_t sbase = smem_u32(dyn);
    int tid = threadIdx.x;
    int m0 = blockIdx.y * 128, n0 = blockIdx.x * 128;
    const bf16* Ag;
    if (splitTT) {
        int b = m0 / TT, t0 = m0 % TT;
        Ag = (t0 < SS) ? A + ((long)(b * SS + t0)) * Kd
                       : A2 + ((long)(b * MM + (t0 - SS))) * Kd;
    } else {
        Ag = A + (long)m0 * Kd;
    }
    const bf16* Bg = Bt + (long)n0 * Kd;
    gemm_body(Ag, Bg, bias, outF, outB, N, Kd, relu, m0, n0, sbase, tid);
}

// dual launch: problem 0 = Q proj (A0 rows), problem 1 = KV proj (split A)
__global__ __launch_bounds__(128, 2)
void mma_gemm_dual(const bf16* __restrict__ A0, const bf16* __restrict__ B0,
                   bf16* __restrict__ O0, int M0, int N0,
                   const bf16* __restrict__ Acache, const bf16* __restrict__ Ah,
                   const bf16* __restrict__ B1, bf16* __restrict__ O1,
                   int M1, int N1, int Kd)
{
    extern __shared__ uint8_t dyn[];
    uint32_t sbase = smem_u32(dyn);
    int tid = threadIdx.x;
    int tiles0 = (M0 / 128) * (N0 / 128);
    if (blockIdx.x < tiles0) {
        int nx = N0 / 128;
        int t = blockIdx.x;
        int m0 = (t / nx) * 128, n0 = (t % nx) * 128;
        gemm_body(A0 + (long)m0 * Kd, B0 + (long)n0 * Kd, nullptr, nullptr, O0,
                  N0, Kd, 0, m0, n0, sbase, tid);
    } else {
        int nx = N1 / 128;
        int t = blockIdx.x - tiles0;
        int m0 = (t / nx) * 128, n0 = (t % nx) * 128;
        int b = m0 / TT, t0 = m0 % TT;
        const bf16* Ag = (t0 < SS) ? Acache + ((long)(b * SS + t0)) * Kd
                                   : Ah + ((long)(b * MM + (t0 - SS))) * Kd;
        gemm_body(Ag, B1 + (long)n0 * Kd, nullptr, nullptr, O1,
                  N1, Kd, 0, m0, n0, sbase, tid);
    }
}

// ---------------- tensor-core flash attention (K|V fused input) ----------------
#define FA_SMEM (8192 + 2*8192 + 2*8192)
__global__ __launch_bounds__(128)
void fa_kernel(const bf16* __restrict__ Q, const bf16* __restrict__ KV,
               const bf16* __restrict__ Ppos, bf16* __restrict__ out)
{
    extern __shared__ uint8_t smemraw[];
    uint32_t sQ = smem_u32(smemraw);
    uint32_t sK = sQ + 8192;
    uint32_t sV = sK + 16384;
    int tid = threadIdx.x, lane = tid & 31, w = tid >> 5;
    int q0 = blockIdx.x * 64;
    int bk = blockIdx.y;
    int b = bk / KH, hh = bk % KH;

    const bf16* Qg = Q + ((long)(b * MM + q0)) * HH + hh * DD;
    const bf16* Kg = KV + ((long)(b * TT + q0)) * KVS + hh * DD;
    const bf16* Vg = Kg + HH;

    #pragma unroll
    for (int i = 0; i < 4; i++) {
        int idx = tid + i * 128;
        int r = idx >> 3, c = idx & 7;
        uint32_t so = (uint32_t)(r * 128 + ((c ^ (r & 7)) << 4));
        CP_ASYNC16(sQ + so, Qg + (long)r * HH + c * 8);
        CP_ASYNC16(sK + so, Kg + (long)r * KVS + c * 8);
        CP_ASYNC16(sV + so, Vg + (long)r * KVS + c * 8);
    }
    CP_COMMIT();

    float Sacc[8][4];
    float Oacc[8][4];
    #pragma unroll
    for (int i = 0; i < 8; i++)
        #pragma unroll
        for (int j = 0; j < 4; j++) Oacc[i][j] = 0.f;
    uint32_t qf[4][4];
    float mrun0 = -1e30f, mrun1 = -1e30f, lrun0 = 0.f, lrun1 = 0.f;

    int r0 = w * 16 + (lane >> 2);
    const bf16* P0 = Ppos + ((long)((b * MM + q0 + r0)) * KH + hh) * SS;
    const bf16* P1 = Ppos + ((long)((b * MM + q0 + r0 + 8)) * KH + hh) * SS;

    for (int t = 0; t < 17; t++) {
        if (t + 1 < 17) {
            uint32_t dstK = sK + ((uint32_t)((t + 1) & 1)) * 8192u;
            uint32_t dstV = sV + ((uint32_t)((t + 1) & 1)) * 8192u;
            const bf16* Kt = Kg + (long)(t + 1) * 64 * KVS;
            const bf16* Vt = Vg + (long)(t + 1) * 64 * KVS;
            #pragma unroll
            for (int i = 0; i < 4; i++) {
                int idx = tid + i * 128;
                int r = idx >> 3, c = idx & 7;
                uint32_t so = (uint32_t)(r * 128 + ((c ^ (r & 7)) << 4));
                CP_ASYNC16(dstK + so, Kt + (long)r * KVS + c * 8);
                CP_ASYNC16(dstV + so, Vt + (long)r * KVS + c * 8);
            }
            CP_COMMIT();
            CP_WAIT(1);
        } else {
            CP_WAIT(0);
        }
        __syncthreads();

        if (t == 0) {
            #pragma unroll
            for (int kt = 0; kt < 4; kt++) {
                int rr = w * 16 + (lane & 15);
                int cc = kt * 2 + (lane >> 4);
                uint32_t addr = sQ + (uint32_t)(rr * 128 + ((cc ^ (rr & 7)) << 4));
                ldsm_x4(qf[kt][0], qf[kt][1], qf[kt][2], qf[kt][3], addr);
            }
        }
        uint32_t kb = sK + ((uint32_t)(t & 1)) * 8192u;
        uint32_t vb = sV + ((uint32_t)(t & 1)) * 8192u;

        #pragma unroll
        for (int i = 0; i < 8; i++) {
            Sacc[i][0] = 0.f; Sacc[i][1] = 0.f; Sacc[i][2] = 0.f; Sacc[i][3] = 0.f;
        }
        #pragma unroll
        for (int kt = 0; kt < 4; kt++) {
            #pragma unroll
            for (int pp = 0; pp < 4; pp++) {
                int rr = pp * 16 + (lane & 15);
                int cc = kt * 2 + (lane >> 4);
                uint32_t addr = kb + (uint32_t)(rr * 128 + ((cc ^ (rr & 7)) << 4));
                uint32_t f0, f1, f2, f3;
                ldsm_x4(f0, f1, f2, f3, addr);
                mma16816(Sacc[2 * pp],     qf[kt], f0, f2);
                mma16816(Sacc[2 * pp + 1], qf[kt], f1, f3);
            }
        }

        float mx0 = -1e30f, mx1 = -1e30f;
        int ubase = t * 64 + (lane & 3) * 2;
        #pragma unroll
        for (int nb = 0; nb < 8; nb++) {
            int u = ubase + nb * 8;
            int j0 = u - r0;
            int j2 = j0 - 8;
            Sacc[nb][0] = (j0 >= 0 && j0 < SS)
                ? (Sacc[nb][0] + __bfloat162float(P0[j0])) * 0.125f : -1e30f;
            Sacc[nb][1] = (j0 + 1 >= 0 && j0 + 1 < SS)
                ? (Sacc[nb][1] + __bfloat162float(P0[j0 + 1])) * 0.125f : -1e30f;
            Sacc[nb][2] = (j2 >= 0 && j2 < SS)
                ? (Sacc[nb][2] + __bfloat162float(P1[j2])) * 0.125f : -1e30f;
            Sacc[nb][3] = (j2 + 1 >= 0 && j2 + 1 < SS)
                ? (Sacc[nb][3] + __bfloat162float(P1[j2 + 1])) * 0.125f : -1e30f;
            mx0 = fmaxf(mx0, fmaxf(Sacc[nb][0], Sacc[nb][1]));
            mx1 = fmaxf(mx1, fmaxf(Sacc[nb][2], Sacc[nb][3]));
        }
        mx0 = fmaxf(mx0, __shfl_xor_sync(0xffffffffu, mx0, 1));
        mx0 = fmaxf(mx0, __shfl_xor_sync(0xffffffffu, mx0, 2));
        mx1 = fmaxf(mx1, __shfl_xor_sync(0xffffffffu, mx1, 1));
        mx1 = fmaxf(mx1, __shfl_xor_sync(0xffffffffu, mx1, 2));
        float mn0 = fmaxf(mrun0, mx0), mn1 = fmaxf(mrun1, mx1);
        float a0 = __expf(mrun0 - mn0), a1 = __expf(mrun1 - mn1);
        float s0 = 0.f, s1 = 0.f;
        #pragma unroll
        for (int nb = 0; nb < 8; nb++) {
            Sacc[nb][0] = __expf(Sacc[nb][0] - mn0);
            Sacc[nb][1] = __expf(Sacc[nb][1] - mn0);
            Sacc[nb][2] = __expf(Sacc[nb][2] - mn1);
            Sacc[nb][3] = __expf(Sacc[nb][3] - mn1);
            s0 += Sacc[nb][0] + Sacc[nb][1];
            s1 += Sacc[nb][2] + Sacc[nb][3];
        }
        s0 += __shfl_xor_sync(0xffffffffu, s0, 1);
        s0 += __shfl_xor_sync(0xffffffffu, s0, 2);
        s1 += __shfl_xor_sync(0xffffffffu, s1, 1);
        s1 += __shfl_xor_sync(0xffffffffu, s1, 2);
        lrun0 = lrun0 * a0 + s0; lrun1 = lrun1 * a1 + s1;
        mrun0 = mn0; mrun1 = mn1;
        #pragma unroll
        for (int i = 0; i < 8; i++) {
            Oacc[i][0] *= a0; Oacc[i][1] *= a0;
            Oacc[i][2] *= a1; Oacc[i][3] *= a1;
        }

        #pragma unroll
        for (int pt = 0; pt < 4; pt++) {
            uint32_t pa[4];
            __nv_bfloat162 p0 = __floats2bfloat162_rn(Sacc[2 * pt][0], Sacc[2 * pt][1]);
            __nv_bfloat162 p1 = __floats2bfloat162_rn(Sacc[2 * pt][2], Sacc[2 * pt][3]);
            __nv_bfloat162 p2 = __floats2bfloat162_rn(Sacc[2 * pt + 1][0], Sacc[2 * pt + 1][1]);
            __nv_bfloat162 p3 = __floats2bfloat162_rn(Sacc[2 * pt + 1][2], Sacc[2 * pt + 1][3]);
            pa[0] = *(uint32_t*)&p0; pa[1] = *(uint32_t*)&p1;
            pa[2] = *(uint32_t*)&p2; pa[3] = *(uint32_t*)&p3;
            #pragma unroll
            for (int db = 0; db < 4; db++) {
                int rr = pt * 16 + (lane & 15);
                int cc = db * 2 + (lane >> 4);
                uint32_t addr = vb + (uint32_t)(rr * 128 + ((cc ^ (rr & 7)) << 4));
                uint32_t f0, f1, f2, f3;
                ldsm_x4_t(f0, f1, f2, f3, addr);
                mma16816(Oacc[2 * db],     pa, f0, f1);
                mma16816(Oacc[2 * db + 1], pa, f2, f3);
            }
        }
        __syncthreads();
    }

    float inv0 = 1.f / lrun0, inv1 = 1.f / lrun1;
    bf16* o0 = out + ((long)(b * MM + q0 + r0)) * HH + hh * DD + (lane & 3) * 2;
    bf16* o1 = out + ((long)(b * MM + q0 + r0 + 8)) * HH + hh * DD + (lane & 3) * 2;
    #pragma unroll
    for (int db = 0; db < 8; db++) {
        __nv_bfloat162 v0 = __floats2bfloat162_rn(Oacc[db][0] * inv0, Oacc[db][1] * inv0);
        __nv_bfloat162 v1 = __floats2bfloat162_rn(Oacc[db][2] * inv1, Oacc[db][3] * inv1);
        *(__nv_bfloat162*)(o0 + db * 8) = v0;
        *(__nv_bfloat162*)(o1 + db * 8) = v1;
    }
}

// ---------------- layernorm of (x + r): fp32 + bf16 out ----------------
__global__ __launch_bounds__(256)
void ln_kernel(const float* __restrict__ x, const float* __restrict__ r,
               const float* __restrict__ s, const float* __restrict__ bta,
               float* __restrict__ out, bf16* __restrict__ outb) {
    __shared__ float sh[32];
    int row = blockIdx.x, tid = threadIdx.x;
    const float* xp = x + (long)row * HH;
    const float* rp = r + (long)row * HH;
    float v0 = xp[tid] + rp[tid];
    float v1 = xp[tid + 256] + rp[tid + 256];
    float v2 = xp[tid + 512] + rp[tid + 512];
    float sum = blockReduceSum(v0 + v1 + v2, sh);
    float mu = sum * (1.f / HH);
    float d0 = v0 - mu, d1 = v1 - mu, d2 = v2 - mu;
    float var = blockReduceSum(d0 * d0 + d1 * d1 + d2 * d2, sh) * (1.f / HH);
    float rstd = rsqrtf(var + 1e-5f);
    float* op = out + (long)row * HH;
    bf16* ob = outb + (long)row * HH;
    float o0 = d0 * rstd * s[tid]       + bta[tid];
    float o1 = d1 * rstd * s[tid + 256] + bta[tid + 256];
    float o2 = d2 * rstd * s[tid + 512] + bta[tid + 512];
    op[tid] = o0; op[tid + 256] = o1; op[tid + 512] = o2;
    ob[tid] = __float2bfloat16_rn(o0);
    ob[tid + 256] = __float2bfloat16_rn(o1);
    ob[tid + 512] = __float2bfloat16_rn(o2);
}

// ---------------- log-softmax: bf16 logits -> fp32 out (one-pass max+sum) --------
__global__ __launch_bounds__(512)
void lsm_bf_kernel(const bf16* __restrict__ logits, float* __restrict__ out) {
    __shared__ float shm[32], shs[32];
    long row = blockIdx.x;
    const uint4* p = (const uint4*)(logits + row * (long)VV);
    int tid = threadIdx.x, lane = tid & 31, w = tid >> 5;
    const int n8 = VV / 8;
    float mx = -1e30f, sm = 0.f;
    for (int i = tid; i < n8; i += 512) {
        uint4 u = p[i];
        float2 a = __bfloat1622float2(*(__nv_bfloat162*)&u.x);
        float2 b = __bfloat1622float2(*(__nv_bfloat162*)&u.y);
        float2 c = __bfloat1622float2(*(__nv_bfloat162*)&u.z);
        float2 d = __bfloat1622float2(*(__nv_bfloat162*)&u.w);
        float m8 = fmaxf(fmaxf(fmaxf(a.x, a.y), fmaxf(b.x, b.y)),
                         fmaxf(fmaxf(c.x, c.y), fmaxf(d.x, d.y)));
        float s8 = __expf(a.x - m8) + __expf(a.y - m8) + __expf(b.x - m8) + __expf(b.y - m8)
                 + __expf(c.x - m8) + __expf(c.y - m8) + __expf(d.x - m8) + __expf(d.y - m8);
        float nm = fmaxf(mx, m8);
        sm = sm * __expf(mx - nm) + s8 * __expf(m8 - nm);
        mx = nm;
    }
    #pragma unroll
    for (int o = 16; o; o >>= 1) {
        float mo = __shfl_xor_sync(0xffffffffu, mx, o);
        float so = __shfl_xor_sync(0xffffffffu, sm, o);
        float nm = fmaxf(mx, mo);
        sm = sm * __expf(mx - nm) + so * __expf(mo - nm);
        mx = nm;
    }
    if (lane == 0) { shm[w] = mx; shs[w] = sm; }
    __syncthreads();
    if (w == 0) {
        mx = (lane < 16) ? shm[lane] : -1e30f;
        sm = (lane < 16) ? shs[lane] : 0.f;
        #pragma unroll
        for (int o = 8; o; o >>= 1) {
            float mo = __shfl_xor_sync(0xffffffffu, mx, o);
            float so = __shfl_xor_sync(0xffffffffu, sm, o);
            float nm = fmaxf(mx, mo);
            sm = sm * __expf(mx - nm) + so * __expf(mo - nm);
            mx = nm;
        }
        if (lane == 0) { shm[0] = mx; shs[0] = sm; }
    }
    __syncthreads();
    float lse = shm[0] + logf(shs[0]);
    float4* o = (float4*)(out + row * (long)VV);
    for (int i = tid; i < n8; i += 512) {
        uint4 u = p[i];
        float2 a = __bfloat1622float2(*(__nv_bfloat162*)&u.x);
        float2 b = __bfloat1622float2(*(__nv_bfloat162*)&u.y);
        float2 c = __bfloat1622float2(*(__nv_bfloat162*)&u.z);
        float2 d = __bfloat1622float2(*(__nv_bfloat162*)&u.w);
        o[2 * i]     = make_float4(a.x - lse, a.y - lse, b.x - lse, b.y - lse);
        o[2 * i + 1] = make_float4(c.x - lse, c.y - lse, d.x - lse, d.y - lse);
    }
}

// ---------------- host orchestration ----------------
static inline void tc_gemm(const bf16* A, const bf16* B, const float* bias,
                           float* outF, bf16* outB, int M, int N, int Kd, int relu) {
    dim3 grid(N / 128, M / 128);
    mma_gemm_kernel<<<grid, 128, GEMM_DSMEM>>>(A, nullptr, B, bias, outF, outB,
                                               M, N, Kd, relu, 0);
}
static inline void transpose_w(const float* W, bf16* Wt, int Kd, int N,
                               int layers, long wstride, long wtstride) {
    dim3 grid(N / 32, Kd / 64, layers);
    transpose_kernel<<<grid, dim3(32, 8)>>>(W, Wt, Kd, N, wstride, wtstride);
}

extern "C" void kernel_launch(void* const* d_in, const int* in_sizes, int n_in,
                              void* d_out, int out_size) {
    const int*   x       = (const int*)  d_in[0];
    const float* h_cache = (const float*)d_in[1];
    const float* key_pe  = (const float*)d_in[2];
    const float* emb     = (const float*)d_in[3];
    const float* Wq      = (const float*)d_in[4];
    const float* Wk      = (const float*)d_in[5];
    const float* Wv      = (const float*)d_in[6];
    const float* Wo      = (const float*)d_in[7];
    const float* fc1_w   = (const float*)d_in[8];
    const float* fc1_b   = (const float*)d_in[9];
    const float* fc2_w   = (const float*)d_in[10];
    const float* fc2_b   = (const float*)d_in[11];
    const float* ln1_s   = (const float*)d_in[12];
    const float* ln1_b   = (const float*)d_in[13];
    const float* ln2_s   = (const float*)d_in[14];
    const float* ln2_b   = (const float*)d_in[15];
    const float* out_w   = (const float*)d_in[16];
    const float* out_b   = (const float*)d_in[17];
    float* out = (float*)d_out;

    float *h, *t2;
    bf16 *pposbf, *logbf, *cachebf;
    bf16 *hbf, *qbf, *kvbf, *aobf, *ffbf, *pet;
    bf16 *wtq, *wtkv, *wto, *wtf1, *wtf2, *wtout;
    cudaGetSymbolAddress((void**)&h,      g_h);
    cudaGetSymbolAddress((void**)&t2,     g_t2);
    cudaGetSymbolAddress((void**)&pposbf, g_pposbf);
    cudaGetSymbolAddress((void**)&logbf,  g_logbf);
    cudaGetSymbolAddress((void**)&cachebf,g_cachebf);
    cudaGetSymbolAddress((void**)&hbf,    g_hbf);
    cudaGetSymbolAddress((void**)&qbf,    g_qbf);
    cudaGetSymbolAddress((void**)&kvbf,   g_kvbf);
    cudaGetSymbolAddress((void**)&aobf,   g_aobf);
    cudaGetSymbolAddress((void**)&ffbf,   g_ffbf);
    cudaGetSymbolAddress((void**)&pet,    g_pet);
    cudaGetSymbolAddress((void**)&wtq,    g_wtq);
    cudaGetSymbolAddress((void**)&wtkv,   g_wtkv);
    cudaGetSymbolAddress((void**)&wto,    g_wto);
    cudaGetSymbolAddress((void**)&wtf1,   g_wtf1);
    cudaGetSymbolAddress((void**)&wtf2,   g_wtf2);
    cudaGetSymbolAddress((void**)&wtout,  g_wtout);

    cudaFuncSetAttribute(mma_gemm_kernel, cudaFuncAttributeMaxDynamicSharedMemorySize, GEMM_DSMEM);
    cudaFuncSetAttribute(mma_gemm_dual,  cudaFuncAttributeMaxDynamicSharedMemorySize, GEMM_DSMEM);
    cudaFuncSetAttribute(fa_kernel, cudaFuncAttributeMaxDynamicSharedMemorySize, FA_SMEM);

    const int rows = BB * MM;   // 4096
    const long hs = (long)HH * HH;
    const long fs = (long)HH * FFD;

    // ---- weight prep (batched over layers) + one-time cache conversion ----
    transpose_w(Wq, wtq, HH, HH, NLAYERS, hs, hs);
    transpose_w(Wk, wtkv,      HH, HH, NLAYERS, hs, 2 * hs);
    transpose_w(Wv, wtkv + hs, HH, HH, NLAYERS, hs, 2 * hs);
    transpose_w(Wo, wto, HH, HH, NLAYERS, hs, hs);
    transpose_w(fc1_w, wtf1, HH, FFD, NLAYERS, fs, fs);
    transpose_w(fc2_w, wtf2, FFD, HH, NLAYERS, fs, fs);
    transpose_w(out_w, wtout, HH, VV, 1, 0, 0);
    transpose_w(key_pe, pet, DD, SS, 1, 0, 0);
    {
        long n4 = (long)NLAYERS * BB * SS * HH / 4;
        conv_cache_kernel<<<(int)((n4 + 255) / 256), 256>>>(h_cache, cachebf, n4);
    }

    embed_kernel<<<rows, 256>>>(x, emb, h, hbf);

    const int tilesQ  = (rows / 128) * (HH / 128);          // 192
    const int tilesKV = (BB * TT / 128) * (KVS / 128);      // 1152

    for (int l = 0; l < NLAYERS; l++) {
        const long wo = (long)l * hs;
        const bf16* cache_l = cachebf + (long)l * BB * SS * HH;

        // fused Q + KV projections in one launch (independent problems)
        mma_gemm_dual<<<tilesQ + tilesKV, 128, GEMM_DSMEM>>>(
            hbf, wtq + wo, qbf, rows, HH,
            cache_l, hbf, wtkv + (long)l * 2 * hs, kvbf, BB * TT, KVS, HH);

        tc_gemm(qbf, pet, nullptr, nullptr, pposbf, rows * KH, SS, DD, 0);

        fa_kernel<<<dim3(MM / 64, BB * KH), 128, FA_SMEM>>>(qbf, kvbf, pposbf, aobf);

        tc_gemm(aobf, wto + wo, nullptr, t2, nullptr, rows, HH, HH, 0);
        ln_kernel<<<rows, 256>>>(h, t2, ln1_s + l * HH, ln1_b + l * HH, h, hbf);

        tc_gemm(hbf,  wtf1 + (long)l * fs, fc1_b + (long)l * FFD, nullptr, ffbf, rows, FFD, HH, 1);
        tc_gemm(ffbf, wtf2 + (long)l * fs, fc2_b + (long)l * HH,  t2, nullptr, rows, HH, FFD, 0);
        ln_kernel<<<rows, 256>>>(h, t2, ln2_s + l * HH, ln2_b + l * HH, h, hbf);
    }

    // vocab projection -> bf16 logits, then log-softmax -> fp32 out
    tc_gemm(hbf, wtout, out_b, nullptr, logbf, rows, VV, HH, 0);
    lsm_bf_kernel<<<rows, 512>>>(logbf, out);
}